// round 9
// baseline (speedup 1.0000x reference)
#include <cuda_runtime.h>
#include <math.h>

// ---------------------------------------------------------------------------
// Problem constants
// ---------------------------------------------------------------------------
namespace {
constexpr int Bn = 64;        // graphs
constexpr int Nn = 512;       // nodes per graph
constexpr int Cc = 128;       // input channels
constexpr int Hh = 128;       // hidden
constexpr int Ed = 5;         // edge dim
constexpr int Ee = 524288;    // edges
constexpr int NT = 32768;     // total nodes
constexpr int K1 = 256;       // clusters pool 1
constexpr int K2 = 128;       // clusters pool 2

// scratch offsets (floats)
constexpr size_t O_QKVS = 0;                           // [NT,512] q|k|v|skip
constexpr size_t O_HF   = O_QKVS + (size_t)NT*512;
constexpr size_t O_S1   = O_HF   + (size_t)NT*Hh;
constexpr size_t O_S1T  = O_S1   + (size_t)NT*K1;      // [Bn][K1][Nn]
constexpr size_t O_T1   = O_S1T  + (size_t)NT*K1;
constexpr size_t O_OX1  = O_T1   + (size_t)NT*K1;
constexpr size_t O_OA1  = O_OX1  + (size_t)Bn*K1*Hh;
constexpr size_t O_D1   = O_OA1  + (size_t)Bn*K1*K1;
constexpr size_t O_AX1  = O_D1   + (size_t)Bn*K1;
constexpr size_t O_XD2  = O_AX1  + (size_t)Bn*K1*Hh;
constexpr size_t O_S2   = O_XD2  + (size_t)Bn*K1*Hh;
constexpr size_t O_S2T  = O_S2   + (size_t)Bn*K1*K2;   // [Bn][K2][K1]
constexpr size_t O_T2   = O_S2T  + (size_t)Bn*K1*K2;
constexpr size_t O_OX2  = O_T2   + (size_t)Bn*K1*K2;
constexpr size_t O_OA2  = O_OX2  + (size_t)Bn*K2*Hh;
constexpr size_t O_D2   = O_OA2  + (size_t)Bn*K2*K2;
constexpr size_t O_AX2  = O_D2   + (size_t)Bn*K2;
constexpr size_t O_XD3  = O_AX2  + (size_t)Bn*K2*Hh;
constexpr size_t O_G    = O_XD3  + (size_t)Bn*K2*Hh;
constexpr size_t O_G1   = O_G    + (size_t)Bn*Hh;
constexpr size_t O_SUM  = O_G1   + (size_t)Bn*Hh;      // bn sums -> scale
constexpr size_t O_SSQ  = O_SUM  + (size_t)Cc;         // bn ssq  -> shift
constexpr size_t O_WCAT = O_SSQ  + (size_t)Cc;
constexpr size_t O_BCAT = O_WCAT + (size_t)Cc*512;
constexpr size_t O_INT  = O_BCAT + 512;

// int offsets (in ints, relative to O_INT)
constexpr size_t I_ADJ  = 0;                 // dstsBySrc [Ee]
constexpr size_t I_PAIR = I_ADJ  + Ee;       // int2 pairs by dst [Ee]
constexpr size_t I_CNT  = I_PAIR + 2*(size_t)Ee;   // cntS|cntD [2NT]
constexpr size_t I_OFFS = I_CNT  + 2*(size_t)NT;
constexpr size_t I_OFFD = I_OFFS + NT + 1;
constexpr size_t I_CURS = I_OFFD + NT + 1;
constexpr size_t I_CURD = I_CURS + NT;
constexpr size_t I_AUX  = I_CURD + NT;
constexpr size_t I_END  = I_AUX  + 256;

constexpr size_t TOTALF = O_INT + I_END + 64;
} // namespace

__device__ float GBUF[TOTALF];

// ---------------------------------------------------------------------------
// Setup: wcat + zero counters + zero bn accumulators (one launch)
// ---------------------------------------------------------------------------
__global__ void setup_kernel(const float* __restrict__ Wq, const float* __restrict__ Wk,
                             const float* __restrict__ Wv, const float* __restrict__ Ws,
                             const float* __restrict__ bq, const float* __restrict__ bk,
                             const float* __restrict__ bv, const float* __restrict__ bs,
                             float* __restrict__ Wcat, float* __restrict__ bcat,
                             int* __restrict__ cnt, float* __restrict__ sums) {
    int idx = blockIdx.x * blockDim.x + threadIdx.x; // 65536 threads
    if (idx < Cc * 512) {
        int k = idx >> 9, j = idx & 511;
        int sel = j >> 7, jj = j & 127;
        const float* W = sel == 0 ? Wq : sel == 1 ? Wk : sel == 2 ? Wv : Ws;
        Wcat[idx] = W[k * Hh + jj];
        if (k == 0) {
            const float* b = sel == 0 ? bq : sel == 1 ? bk : sel == 2 ? bv : bs;
            bcat[j] = b[jj];
        }
        cnt[idx] = 0;                    // 2*NT == 65536
        if (idx < 2 * Cc) sums[idx] = 0.f;
    }
}

// ---------------------------------------------------------------------------
// BatchNorm: reduce, then stats -> scale/shift (in place over sum/ssq)
// ---------------------------------------------------------------------------
__global__ void bn_reduce_kernel(const float* __restrict__ x, float* __restrict__ sum,
                                 float* __restrict__ ssq) {
    int c = threadIdx.x;
    float s = 0.f, ss = 0.f;
    for (int r = blockIdx.x; r < NT; r += gridDim.x) {
        float v = x[(size_t)r * Cc + c];
        s += v; ss += v * v;
    }
    atomicAdd(&sum[c], s);
    atomicAdd(&ssq[c], ss);
}

__global__ void bn_stats_kernel(float* __restrict__ sum, float* __restrict__ ssq,
                                const float* __restrict__ gamma, const float* __restrict__ beta) {
    int c = threadIdx.x; // 128
    float mu  = sum[c] * (1.f / NT);
    float var = ssq[c] * (1.f / NT) - mu * mu;
    float sc  = gamma[c] * rsqrtf(var + 1e-5f);
    sum[c] = sc;                     // scale
    ssq[c] = beta[c] - mu * sc;      // shift
}

// ---------------------------------------------------------------------------
// Pre-split 3xTF32 tensor-core GEMM: C = act((A*as+ash)*B [+ A2*B2] + bias + Cadd)
// Block tile 128x128, 8 warps (4M x 2N), warp tile 32x64 (f=2, g=8).
// ---------------------------------------------------------------------------
__device__ __forceinline__ unsigned tf32_of(float v) {
    unsigned h;
    asm("cvt.rna.tf32.f32 %0, %1;" : "=r"(h) : "f"(v));
    return h;
}

__device__ __forceinline__ void mma_tf32(float4& c, unsigned a0, unsigned a1, unsigned a2,
                                         unsigned a3, unsigned b0, unsigned b1) {
    asm volatile(
        "mma.sync.aligned.m16n8k8.row.col.f32.tf32.tf32.f32 "
        "{%0,%1,%2,%3}, {%4,%5,%6,%7}, {%8,%9}, {%0,%1,%2,%3};"
        : "+f"(c.x), "+f"(c.y), "+f"(c.z), "+f"(c.w)
        : "r"(a0), "r"(a1), "r"(a2), "r"(a3), "r"(b0), "r"(b1));
}

template <int ACT, bool DUAL, bool BNA>
__global__ void __launch_bounds__(256)
gemm_tc_kernel(const float* __restrict__ A, const float* __restrict__ Bm,
               const float* __restrict__ A2, const float* __restrict__ B2,
               float* __restrict__ C, const float* __restrict__ bias,
               const float* __restrict__ Cadd,
               const float* __restrict__ ascale, const float* __restrict__ ashift,
               int M, int N, int K, int lda, int ldb, int ldc,
               long sA, long sB, long sC) {
    constexpr int BM = 128, BN = 128, BK = 16, LD = 20;
    __shared__ unsigned Ahi[BM][LD], Alo[BM][LD];
    __shared__ unsigned Bhi[BN][LD], Blo[BN][LD];

    int bz = blockIdx.z;
    const float* Cad = Cadd ? Cadd + (size_t)bz * sC : nullptr;
    C += (size_t)bz * sC;

    int m0 = blockIdx.y * BM, n0 = blockIdx.x * BN;
    int t = threadIdx.x;
    int warp = t >> 5, lane = t & 31;
    int wm = (warp & 3) * 32;     // 4 warps in M
    int wn = (warp >> 2) * 64;    // 2 warps in N, 64 cols each
    int rr = lane >> 2, cc = lane & 3;

    float4 acc[2][8];
#pragma unroll
    for (int f = 0; f < 2; f++)
#pragma unroll
        for (int g = 0; g < 8; g++) acc[f][g] = make_float4(0.f, 0.f, 0.f, 0.f);

    for (int pass = 0; pass < (DUAL ? 2 : 1); pass++) {
        const float* Ap = (pass == 0) ? A + (size_t)bz * sA : A2;
        const float* Bp = (pass == 0) ? Bm + (size_t)bz * sB : B2;

        for (int k0 = 0; k0 < K; k0 += BK) {
            // --- A tile: thread loads 8 consecutive k of one m-row ---
            {
                int m = t >> 1, k8 = (t & 1) * 8;
                const float* ap = &Ap[(size_t)(m0 + m) * lda + k0 + k8];
                float4 v0 = *(const float4*)ap;
                float4 v1 = *(const float4*)(ap + 4);
                float vv[8] = {v0.x, v0.y, v0.z, v0.w, v1.x, v1.y, v1.z, v1.w};
                if (BNA) {
#pragma unroll
                    for (int i = 0; i < 8; i++)
                        vv[i] = vv[i] * __ldg(&ascale[k0 + k8 + i]) + __ldg(&ashift[k0 + k8 + i]);
                }
                unsigned hi[8], lo[8];
#pragma unroll
                for (int i = 0; i < 8; i++) {
                    hi[i] = tf32_of(vv[i]);
                    lo[i] = tf32_of(vv[i] - __uint_as_float(hi[i]));
                }
                *(uint4*)&Ahi[m][k8]     = make_uint4(hi[0], hi[1], hi[2], hi[3]);
                *(uint4*)&Ahi[m][k8 + 4] = make_uint4(hi[4], hi[5], hi[6], hi[7]);
                *(uint4*)&Alo[m][k8]     = make_uint4(lo[0], lo[1], lo[2], lo[3]);
                *(uint4*)&Alo[m][k8 + 4] = make_uint4(lo[4], lo[5], lo[6], lo[7]);
            }
            // --- B tile: [K,N] row-major; thread covers 8 n at fixed k ---
            {
                int k = t >> 4, nb = t & 15;
                const float* brow = &Bp[(size_t)(k0 + k) * ldb + n0];
#pragma unroll
                for (int i = 0; i < 8; i++) {
                    int n = nb + 16 * i;
                    float v = brow[n];
                    unsigned h = tf32_of(v);
                    Bhi[n][k] = h;
                    Blo[n][k] = tf32_of(v - __uint_as_float(h));
                }
            }
            __syncthreads();

#pragma unroll
            for (int kk = 0; kk < BK; kk += 8) {
                unsigned ah[2][4], al[2][4];
#pragma unroll
                for (int f = 0; f < 2; f++) {
                    int r = wm + 16 * f + rr;
                    ah[f][0] = Ahi[r][kk + cc];       ah[f][1] = Ahi[r + 8][kk + cc];
                    ah[f][2] = Ahi[r][kk + cc + 4];   ah[f][3] = Ahi[r + 8][kk + cc + 4];
                    al[f][0] = Alo[r][kk + cc];       al[f][1] = Alo[r + 8][kk + cc];
                    al[f][2] = Alo[r][kk + cc + 4];   al[f][3] = Alo[r + 8][kk + cc + 4];
                }
#pragma unroll
                for (int g = 0; g < 8; g++) {
                    int n = wn + 8 * g + rr;
                    unsigned b0 = Bhi[n][kk + cc], b1 = Bhi[n][kk + cc + 4];
                    unsigned c0 = Blo[n][kk + cc], c1 = Blo[n][kk + cc + 4];
#pragma unroll
                    for (int f = 0; f < 2; f++) {
                        mma_tf32(acc[f][g], ah[f][0], ah[f][1], ah[f][2], ah[f][3], b0, b1);
                        mma_tf32(acc[f][g], ah[f][0], ah[f][1], ah[f][2], ah[f][3], c0, c1);
                        mma_tf32(acc[f][g], al[f][0], al[f][1], al[f][2], al[f][3], b0, b1);
                    }
                }
            }
            __syncthreads();
        }
    }

    // --- epilogue ---
#pragma unroll
    for (int f = 0; f < 2; f++) {
#pragma unroll
        for (int g = 0; g < 8; g++) {
            int r0 = m0 + wm + 16 * f + rr;
            int c0 = n0 + wn + 8 * g + cc * 2;
            float bx = 0.f, by = 0.f;
            if (bias) { bx = bias[c0]; by = bias[c0 + 1]; }
            float2 top = make_float2(acc[f][g].x + bx, acc[f][g].y + by);
            float2 bot = make_float2(acc[f][g].z + bx, acc[f][g].w + by);
            size_t offT = (size_t)r0 * ldc + c0;
            size_t offB = (size_t)(r0 + 8) * ldc + c0;
            if (Cad) {
                float2 t0 = *(const float2*)&Cad[offT];
                float2 t1 = *(const float2*)&Cad[offB];
                top.x += t0.x; top.y += t0.y;
                bot.x += t1.x; bot.y += t1.y;
            }
            if (ACT == 1) {
                top.x = fmaxf(top.x, 0.f); top.y = fmaxf(top.y, 0.f);
                bot.x = fmaxf(bot.x, 0.f); bot.y = fmaxf(bot.y, 0.f);
            }
            *(float2*)&C[offT] = top;
            *(float2*)&C[offB] = bot;
        }
    }
}

// ---------------------------------------------------------------------------
// CSR build
// ---------------------------------------------------------------------------
__global__ void csr_count_kernel(const int* __restrict__ src, const int* __restrict__ dst,
                                 int* __restrict__ cnt) {
    int e = blockIdx.x * blockDim.x + threadIdx.x;
    if (e >= Ee) return;
    atomicAdd(&cnt[src[e]], 1);
    atomicAdd(&cnt[NT + dst[e]], 1);
}

__global__ void scan_chunk_kernel(const int* __restrict__ cnt, int* __restrict__ excl,
                                  int* __restrict__ aux) {
    __shared__ int sm[256];
    int c = blockIdx.x, t = threadIdx.x;
    int v = cnt[c * 256 + t];
    sm[t] = v;
    __syncthreads();
    for (int d = 1; d < 256; d <<= 1) {
        int u = (t >= d) ? sm[t - d] : 0;
        __syncthreads();
        sm[t] += u;
        __syncthreads();
    }
    excl[c * 256 + t] = sm[t] - v;
    if (t == 255) aux[c] = sm[255];
}

__global__ void scan_aux_kernel(int* __restrict__ aux) {
    __shared__ int sm[256];
    int t = threadIdx.x;
    int i = t & 127;
    int v = aux[t];
    sm[t] = v;
    __syncthreads();
    for (int d = 1; d < 128; d <<= 1) {
        int u = (i >= d) ? sm[t - d] : 0;
        __syncthreads();
        sm[t] += u;
        __syncthreads();
    }
    aux[t] = sm[t] - v;
}

__global__ void scan_final_kernel(const int* __restrict__ excl, const int* __restrict__ aux,
                                  int* __restrict__ offS, int* __restrict__ curS,
                                  int* __restrict__ offD, int* __restrict__ curD) {
    int c = blockIdx.x, t = threadIdx.x;
    int idx = c * 256 + t;
    int v = excl[idx] + aux[c];
    if (idx < NT) { offS[idx] = v; curS[idx] = v; }
    else          { offD[idx - NT] = v; curD[idx - NT] = v; }
    if (idx == 0) { offS[NT] = Ee; offD[NT] = Ee; }
}

__global__ void csr_scatter_kernel(const int* __restrict__ src, const int* __restrict__ dst,
                                   int* __restrict__ curS, int* __restrict__ curD,
                                   int* __restrict__ dstsBySrc, int2* __restrict__ pairByDst) {
    int e = blockIdx.x * blockDim.x + threadIdx.x;
    if (e >= Ee) return;
    int s = src[e], d = dst[e];
    int ps = atomicAdd(&curS[s], 1);
    dstsBySrc[ps] = d;
    int pd = atomicAdd(&curD[d], 1);
    pairByDst[pd] = make_int2(s, e);
}

// ---------------------------------------------------------------------------
// Fused TransformerConv — vectorized: lane owns h in [lane*4, lane*4+4)
// ---------------------------------------------------------------------------
__global__ void attn_fused_kernel(const int* __restrict__ offD, const int2* __restrict__ pair,
                                  const float* __restrict__ ea, const float* __restrict__ We,
                                  const float* __restrict__ qkvs, float* __restrict__ h) {
    __shared__ float sWe[Ed * Hh];
    for (int i = threadIdx.x; i < Ed * Hh; i += blockDim.x) sWe[i] = We[i];
    __syncthreads();
    int d = blockIdx.x * (blockDim.x >> 5) + (threadIdx.x >> 5);
    int lane = threadIdx.x & 31;
    if (d >= NT) return;

    float4 qv  = *(const float4*)&qkvs[(size_t)d * 512 + lane * 4];
    float4 we0 = *(const float4*)&sWe[0 * Hh + lane * 4];
    float4 we1 = *(const float4*)&sWe[1 * Hh + lane * 4];
    float4 we2 = *(const float4*)&sWe[2 * Hh + lane * 4];
    float4 we3 = *(const float4*)&sWe[3 * Hh + lane * 4];
    float4 we4 = *(const float4*)&sWe[4 * Hh + lane * 4];

    float m = -1e30f, ssum = 0.f;
    float4 acc = make_float4(0.f, 0.f, 0.f, 0.f);

    int beg = offD[d], end = offD[d + 1];
    for (int i = beg; i < end; i++) {
        int2 p = pair[i];
        const float* eap = ea + (size_t)p.y * 5;
        float a0 = eap[0], a1 = eap[1], a2 = eap[2], a3 = eap[3], a4 = eap[4];
        float4 ev;
        ev.x = a0 * we0.x + a1 * we1.x + a2 * we2.x + a3 * we3.x + a4 * we4.x;
        ev.y = a0 * we0.y + a1 * we1.y + a2 * we2.y + a3 * we3.y + a4 * we4.y;
        ev.z = a0 * we0.z + a1 * we1.z + a2 * we2.z + a3 * we3.z + a4 * we4.z;
        ev.w = a0 * we0.w + a1 * we1.w + a2 * we2.w + a3 * we3.w + a4 * we4.w;
        const float4 kv = *(const float4*)&qkvs[(size_t)p.x * 512 + 128 + lane * 4];
        const float4 vv = *(const float4*)&qkvs[(size_t)p.x * 512 + 256 + lane * 4];
        float dot = qv.x * (kv.x + ev.x) + qv.y * (kv.y + ev.y) +
                    qv.z * (kv.z + ev.z) + qv.w * (kv.w + ev.w);
#pragma unroll
        for (int o = 16; o > 0; o >>= 1) dot += __shfl_xor_sync(0xffffffffu, dot, o);
        float lg = dot * 0.08838834764831845f;
        float mn = fmaxf(m, lg);
        float sc = __expf(m - mn);
        float pw = __expf(lg - mn);
        ssum = ssum * sc + pw;
        acc.x = acc.x * sc + pw * (vv.x + ev.x);
        acc.y = acc.y * sc + pw * (vv.y + ev.y);
        acc.z = acc.z * sc + pw * (vv.z + ev.z);
        acc.w = acc.w * sc + pw * (vv.w + ev.w);
        m = mn;
    }
    float inv = (ssum > 0.f) ? 1.f / ssum : 0.f;
    float4 skip = *(const float4*)&qkvs[(size_t)d * 512 + 384 + lane * 4];
    float4 o;
    o.x = fmaxf(acc.x * inv + skip.x, 0.f);
    o.y = fmaxf(acc.y * inv + skip.y, 0.f);
    o.z = fmaxf(acc.z * inv + skip.z, 0.f);
    o.w = fmaxf(acc.w * inv + skip.w, 0.f);
    *(float4*)&h[(size_t)d * Hh + lane * 4] = o;
}

// ---------------------------------------------------------------------------
// T1 = adj @ s1 via CSR gather — vectorized float4
// ---------------------------------------------------------------------------
__global__ void t1_gather_kernel(const int* __restrict__ offS, const int* __restrict__ dstsBySrc,
                                 const float* __restrict__ s1, float* __restrict__ T1) {
    int s = blockIdx.x * (blockDim.x >> 5) + (threadIdx.x >> 5);
    int lane = threadIdx.x & 31;
    if (s >= NT) return;
    float4 a0 = make_float4(0.f, 0.f, 0.f, 0.f);
    float4 a1 = make_float4(0.f, 0.f, 0.f, 0.f);
    int beg = offS[s], end = offS[s + 1];
    for (int i = beg; i < end; i++) {
        const float4* row = (const float4*)(s1 + (size_t)dstsBySrc[i] * K1);
        float4 r0 = row[lane], r1 = row[lane + 32];
        a0.x += r0.x; a0.y += r0.y; a0.z += r0.z; a0.w += r0.w;
        a1.x += r1.x; a1.y += r1.y; a1.z += r1.z; a1.w += r1.w;
    }
    float4* trow = (float4*)(T1 + (size_t)s * K1);
    trow[lane] = a0;
    trow[lane + 32] = a1;
}

// ---------------------------------------------------------------------------
// Per-graph tiled transpose
// ---------------------------------------------------------------------------
__global__ void transpose_pg_kernel(const float* __restrict__ in, float* __restrict__ outp,
                                    int R, int Cq) {
    __shared__ float tile[32][33];
    int b = blockIdx.z;
    int c0 = blockIdx.x * 32, r0 = blockIdx.y * 32;
    int tx = threadIdx.x, ty = threadIdx.y;
    const float* ip = in + (size_t)b * R * Cq;
    float* op = outp + (size_t)b * R * Cq;
#pragma unroll
    for (int i = 0; i < 32; i += 8)
        tile[ty + i][tx] = ip[(size_t)(r0 + ty + i) * Cq + c0 + tx];
    __syncthreads();
#pragma unroll
    for (int i = 0; i < 32; i += 8)
        op[(size_t)(c0 + ty + i) * R + r0 + tx] = tile[tx][ty + i];
}

// ---------------------------------------------------------------------------
// small FFMA GEMM for readout
// ---------------------------------------------------------------------------
template <int ACT>
__global__ void gemm64_kernel(const float* __restrict__ A, const float* __restrict__ Bm,
                              float* __restrict__ C, const float* __restrict__ bias,
                              int M, int N, int K, int lda, int ldb, int ldc) {
    constexpr int BM = 64, BN = 64, BK = 16;
    __shared__ float As[BK][BM + 1];
    __shared__ float Bs[BK][BN];
    int m0 = blockIdx.y * BM, n0 = blockIdx.x * BN;
    int t = threadIdx.x;
    int tx = t & 15, ty = t >> 4;
    float acc[4][4] = {};
    for (int k0 = 0; k0 < K; k0 += BK) {
        {
            int mm = t >> 2, kk = (t & 3) << 2;
            const float4 av = *(const float4*)&A[(size_t)(m0 + mm) * lda + k0 + kk];
            As[kk + 0][mm] = av.x; As[kk + 1][mm] = av.y;
            As[kk + 2][mm] = av.z; As[kk + 3][mm] = av.w;
        }
        {
            int kk = t >> 4, nn = (t & 15) << 2;
            *(float4*)&Bs[kk][nn] = *(const float4*)&Bm[(size_t)(k0 + kk) * ldb + n0 + nn];
        }
        __syncthreads();
#pragma unroll
        for (int kk = 0; kk < BK; kk++) {
            float a0 = As[kk][ty * 4 + 0], a1 = As[kk][ty * 4 + 1];
            float a2 = As[kk][ty * 4 + 2], a3 = As[kk][ty * 4 + 3];
            float4 b = *(const float4*)&Bs[kk][tx * 4];
            acc[0][0] += a0 * b.x; acc[0][1] += a0 * b.y; acc[0][2] += a0 * b.z; acc[0][3] += a0 * b.w;
            acc[1][0] += a1 * b.x; acc[1][1] += a1 * b.y; acc[1][2] += a1 * b.z; acc[1][3] += a1 * b.w;
            acc[2][0] += a2 * b.x; acc[2][1] += a2 * b.y; acc[2][2] += a2 * b.z; acc[2][3] += a2 * b.w;
            acc[3][0] += a3 * b.x; acc[3][1] += a3 * b.y; acc[3][2] += a3 * b.z; acc[3][3] += a3 * b.w;
        }
        __syncthreads();
    }
#pragma unroll
    for (int i = 0; i < 4; i++) {
        int m = m0 + ty * 4 + i;
        size_t off = (size_t)m * ldc + n0 + tx * 4;
        float4 r = make_float4(acc[i][0], acc[i][1], acc[i][2], acc[i][3]);
        if (bias) {
            int nb = n0 + tx * 4;
            r.x += bias[nb + 0]; r.y += bias[nb + 1];
            r.z += bias[nb + 2]; r.w += bias[nb + 3];
        }
        if (ACT == 1) {
            r.x = fmaxf(r.x, 0.f); r.y = fmaxf(r.y, 0.f);
            r.z = fmaxf(r.z, 0.f); r.w = fmaxf(r.w, 0.f);
        }
        *(float4*)&C[off] = r;
    }
}

// ---------------------------------------------------------------------------
// Softmax over rows
// ---------------------------------------------------------------------------
__global__ void softmax_rows_kernel(float* __restrict__ X, int rows, int cols) {
    int row = blockIdx.x * (blockDim.x >> 5) + (threadIdx.x >> 5);
    int lane = threadIdx.x & 31;
    if (row >= rows) return;
    float* p = X + (size_t)row * cols;
    float mx = -1e30f;
    for (int c = lane; c < cols; c += 32) mx = fmaxf(mx, p[c]);
#pragma unroll
    for (int o = 16; o > 0; o >>= 1) mx = fmaxf(mx, __shfl_xor_sync(0xffffffffu, mx, o));
    float sum = 0.f;
    for (int c = lane; c < cols; c += 32) {
        float v = __expf(p[c] - mx);
        p[c] = v;
        sum += v;
    }
#pragma unroll
    for (int o = 16; o > 0; o >>= 1) sum += __shfl_xor_sync(0xffffffffu, sum, o);
    float inv = 1.f / sum;
    for (int c = lane; c < cols; c += 32) p[c] *= inv;
}

// ---------------------------------------------------------------------------
// out_adj normalization
// ---------------------------------------------------------------------------
__global__ void adj_rowsum_kernel(float* __restrict__ A, float* __restrict__ d, int Kd) {
    int b = blockIdx.y, i = blockIdx.x, tid = threadIdx.x;
    float* row = A + ((size_t)b * Kd + i) * Kd;
    float v = row[tid];
    if (tid == i) { v = 0.f; row[tid] = 0.f; }
    __shared__ float sh[256];
    sh[tid] = v;
    __syncthreads();
    for (int s = Kd >> 1; s > 0; s >>= 1) {
        if (tid < s) sh[tid] += sh[tid + s];
        __syncthreads();
    }
    if (tid == 0) d[(size_t)b * Kd + i] = sqrtf(sh[0]) + 1e-15f;
}

__global__ void adj_divide_kernel(float* __restrict__ A, const float* __restrict__ d, int Kd,
                                  size_t total) {
    size_t i = (size_t)blockIdx.x * blockDim.x + threadIdx.x;
    if (i >= total) return;
    int j = (int)(i % Kd);
    size_t bi = i / Kd;
    int ii = (int)(bi % Kd);
    int b = (int)(bi / Kd);
    A[i] = A[i] / (d[(size_t)b * Kd + ii] * d[(size_t)b * Kd + j]);
}

// ---------------------------------------------------------------------------
// Readout
// ---------------------------------------------------------------------------
__global__ void mean_nodes_kernel(const float* __restrict__ xd, float* __restrict__ g) {
    int b = blockIdx.x, f = threadIdx.x;
    float s = 0.f;
    for (int n = 0; n < K2; n++) s += xd[((size_t)b * K2 + n) * Hh + f];
    g[(size_t)b * Hh + f] = s * (1.f / K2);
}

__global__ void readout_kernel(const float* __restrict__ g1, const float* __restrict__ Wro,
                               const float* __restrict__ bro, float* __restrict__ out) {
    int b = blockIdx.x, lane = threadIdx.x;
    float s = 0.f;
    for (int j = lane; j < Hh; j += 32) s += g1[(size_t)b * Hh + j] * Wro[j];
#pragma unroll
    for (int o = 16; o > 0; o >>= 1) s += __shfl_xor_sync(0xffffffffu, s, o);
    if (lane == 0) out[b] = 1.f / (1.f + expf(-(s + bro[0])));
}

// ---------------------------------------------------------------------------
// Host side
// ---------------------------------------------------------------------------
static void launch_gemm(int act, const float* A, const float* B, float* C,
                        const float* bias, const float* Cadd, int M, int N, int K, int lda,
                        int ldb, int ldc, long sA, long sB, long sC, int batch) {
    dim3 grid(N / 128, M / 128, batch), block(256);
    if (act == 1) {
        gemm_tc_kernel<1, false, false><<<grid, block>>>(A, B, nullptr, nullptr, C, bias, Cadd,
                                                         nullptr, nullptr,
                                                         M, N, K, lda, ldb, ldc, sA, sB, sC);
    } else {
        gemm_tc_kernel<0, false, false><<<grid, block>>>(A, B, nullptr, nullptr, C, bias, Cadd,
                                                         nullptr, nullptr,
                                                         M, N, K, lda, ldb, ldc, sA, sB, sC);
    }
}

static void launch_gemm_dual(int act, const float* A, const float* B, const float* A2,
                             const float* B2, float* C, const float* bias, int M, int N, int K,
                             int ld) {
    dim3 grid(N / 128, M / 128, 1), block(256);
    if (act == 1) {
        gemm_tc_kernel<1, true, false><<<grid, block>>>(A, B, A2, B2, C, bias, nullptr,
                                                        nullptr, nullptr,
                                                        M, N, K, ld, N, N, 0, 0, 0);
    } else {
        gemm_tc_kernel<0, true, false><<<grid, block>>>(A, B, A2, B2, C, bias, nullptr,
                                                        nullptr, nullptr,
                                                        M, N, K, ld, N, N, 0, 0, 0);
    }
}

extern "C" void kernel_launch(void* const* d_in, const int* in_sizes, int n_in,
                              void* d_out, int out_size) {
    const float* x      = (const float*)d_in[0];
    const int*   ei     = (const int*)d_in[1];
    const float* ea     = (const float*)d_in[2];
    const float* bng    = (const float*)d_in[4];
    const float* bnb    = (const float*)d_in[5];
    const float* Wq     = (const float*)d_in[6];
    const float* bq     = (const float*)d_in[7];
    const float* Wk     = (const float*)d_in[8];
    const float* bk     = (const float*)d_in[9];
    const float* Wv     = (const float*)d_in[10];
    const float* bv     = (const float*)d_in[11];
    const float* We     = (const float*)d_in[12];
    const float* Wskip  = (const float*)d_in[13];
    const float* bskip  = (const float*)d_in[14];
    const float* Wm1    = (const float*)d_in[15];
    const float* bm1    = (const float*)d_in[16];
    const float* W2rel  = (const float*)d_in[17];
    const float* b2rel  = (const float*)d_in[18];
    const float* W2root = (const float*)d_in[19];
    const float* Wm2    = (const float*)d_in[20];
    const float* bm2    = (const float*)d_in[21];
    const float* W3rel  = (const float*)d_in[22];
    const float* b3rel  = (const float*)d_in[23];
    const float* W3root = (const float*)d_in[24];
    const float* Wlin1  = (const float*)d_in[25];
    const float* blin1  = (const float*)d_in[26];
    const float* Wro    = (const float*)d_in[27];
    const float* bro    = (const float*)d_in[28];
    float* out = (float*)d_out;

    const int* src = ei;
    const int* dst = ei + Ee;

    float* gb = nullptr;
    cudaGetSymbolAddress((void**)&gb, GBUF);
    int* ib = (int*)(gb + O_INT);

    int*  cnt  = ib + I_CNT;
    int*  offS = ib + I_OFFS;
    int*  offD = ib + I_OFFD;
    int*  curS = ib + I_CURS;
    int*  curD = ib + I_CURD;
    int*  aux  = ib + I_AUX;
    int*  adjS = ib + I_ADJ;
    int2* pair = (int2*)(ib + I_PAIR);

    // launch 1: setup (wcat + zero cnt + zero bn sums)
    setup_kernel<<<(Cc * 512) / 256, 256>>>(Wq, Wk, Wv, Wskip, bq, bk, bv, bskip,
                                            gb + O_WCAT, gb + O_BCAT, cnt, gb + O_SUM);
    // launch 2-3: BatchNorm stats
    bn_reduce_kernel<<<256, Cc>>>(x, gb + O_SUM, gb + O_SSQ);
    bn_stats_kernel<<<1, Cc>>>(gb + O_SUM, gb + O_SSQ, bng, bnb);
    // launch 4: qkvs GEMM with fused BN prologue (PROFILED under -s 5 -c 1)
    {
        dim3 grid(512 / 128, NT / 128, 1), block(256);
        gemm_tc_kernel<0, false, true><<<grid, block>>>(
            x, gb + O_WCAT, nullptr, nullptr, gb + O_QKVS, gb + O_BCAT, nullptr,
            gb + O_SUM, gb + O_SSQ, NT, 512, Cc, Cc, 512, 512, 0, 0, 0);
    }

    // ---- CSR build ----
    csr_count_kernel<<<Ee / 256, 256>>>(src, dst, cnt);
    scan_chunk_kernel<<<256, 256>>>(cnt, ib + I_CURS, aux);
    scan_aux_kernel<<<1, 256>>>(aux);
    scan_final_kernel<<<256, 256>>>(ib + I_CURS, aux, offS, curS, offD, curD);
    csr_scatter_kernel<<<Ee / 256, 256>>>(src, dst, curS, curD, adjS, pair);

    // ---- fused attention ----
    attn_fused_kernel<<<NT / 8, 256>>>(offD, pair, ea, We, gb + O_QKVS, gb + O_HF);

    // ---- pool 1 ----
    launch_gemm(0, gb + O_HF, Wm1, gb + O_S1, bm1, nullptr,
                NT, K1, Hh, Hh, K1, K1, 0, 0, 0, 1);
    softmax_rows_kernel<<<NT / 8, 256>>>(gb + O_S1, NT, K1);

    {
        dim3 g(K1 / 32, Nn / 32, Bn), bdim(32, 8);
        transpose_pg_kernel<<<g, bdim>>>(gb + O_S1, gb + O_S1T, Nn, K1);
    }

    t1_gather_kernel<<<NT / 8, 256>>>(offS, adjS, gb + O_S1, gb + O_T1);

    launch_gemm(0, gb + O_S1T, gb + O_HF, gb + O_OX1, nullptr, nullptr,
                K1, Hh, Nn, Nn, Hh, Hh, (long)K1 * Nn, (long)Nn * Hh, (long)K1 * Hh, Bn);
    launch_gemm(0, gb + O_S1T, gb + O_T1, gb + O_OA1, nullptr, nullptr,
                K1, K1, Nn, Nn, K1, K1, (long)K1 * Nn, (long)Nn * K1, (long)K1 * K1, Bn);

    {
        dim3 g1(K1, Bn);
        adj_rowsum_kernel<<<g1, K1>>>(gb + O_OA1, gb + O_D1, K1);
        size_t tot = (size_t)Bn * K1 * K1;
        adj_divide_kernel<<<(int)((tot + 255) / 256), 256>>>(gb + O_OA1, gb + O_D1, K1, tot);
    }

    // ---- DenseGraphConv 2 ----
    launch_gemm(0, gb + O_OA1, gb + O_OX1, gb + O_AX1, nullptr, nullptr,
                K1, Hh, K1, K1, Hh, Hh, (long)K1 * K1, (long)K1 * Hh, (long)K1 * Hh, Bn);
    launch_gemm_dual(1, gb + O_AX1, W2rel, gb + O_OX1, W2root, gb + O_XD2, b2rel,
                     Bn * K1, Hh, Hh, Hh);

    // ---- pool 2 ----
    launch_gemm(0, gb + O_XD2, Wm2, gb + O_S2, bm2, nullptr,
                Bn * K1, K2, Hh, Hh, K2, K2, 0, 0, 0, 1);
    softmax_rows_kernel<<<(Bn * K1) / 8, 256>>>(gb + O_S2, Bn * K1, K2);

    {
        dim3 g(K2 / 32, K1 / 32, Bn), bdim(32, 8);
        transpose_pg_kernel<<<g, bdim>>>(gb + O_S2, gb + O_S2T, K1, K2);
    }

    launch_gemm(0, gb + O_S2T, gb + O_XD2, gb + O_OX2, nullptr, nullptr,
                K2, Hh, K1, K1, Hh, Hh, (long)K2 * K1, (long)K1 * Hh, (long)K2 * Hh, Bn);
    launch_gemm(0, gb + O_OA1, gb + O_S2, gb + O_T2, nullptr, nullptr,
                K1, K2, K1, K1, K2, K2, (long)K1 * K1, (long)K1 * K2, (long)K1 * K2, Bn);
    launch_gemm(0, gb + O_S2T, gb + O_T2, gb + O_OA2, nullptr, nullptr,
                K2, K2, K1, K1, K2, K2, (long)K2 * K1, (long)K1 * K2, (long)K2 * K2, Bn);

    {
        dim3 g2(K2, Bn);
        adj_rowsum_kernel<<<g2, K2>>>(gb + O_OA2, gb + O_D2, K2);
        size_t tot = (size_t)Bn * K2 * K2;
        adj_divide_kernel<<<(int)((tot + 255) / 256), 256>>>(gb + O_OA2, gb + O_D2, K2, tot);
    }

    // ---- DenseGraphConv 3 ----
    launch_gemm(0, gb + O_OA2, gb + O_OX2, gb + O_AX2, nullptr, nullptr,
                K2, Hh, K2, K2, Hh, Hh, (long)K2 * K2, (long)K2 * Hh, (long)K2 * Hh, Bn);
    launch_gemm_dual(0, gb + O_AX2, W3rel, gb + O_OX2, W3root, gb + O_XD3, b3rel,
                     Bn * K2, Hh, Hh, Hh);

    // ---- readout ----
    mean_nodes_kernel<<<Bn, Hh>>>(gb + O_XD3, gb + O_G);
    gemm64_kernel<1><<<dim3(2, 1), 256>>>(gb + O_G, Wlin1, gb + O_G1, blin1,
                                          Bn, Hh, Hh, Hh, Hh, Hh);
    readout_kernel<<<Bn, 32>>>(gb + O_G1, Wro, bro, out);
}

// round 11
// speedup vs baseline: 1.0030x; 1.0030x over previous
#include <cuda_runtime.h>
#include <math.h>

// ---------------------------------------------------------------------------
// Problem constants
// ---------------------------------------------------------------------------
namespace {
constexpr int Bn = 64;        // graphs
constexpr int Nn = 512;       // nodes per graph
constexpr int Cc = 128;       // input channels
constexpr int Hh = 128;       // hidden
constexpr int Ed = 5;         // edge dim
constexpr int Ee = 524288;    // edges
constexpr int NT = 32768;     // total nodes
constexpr int K1 = 256;       // clusters pool 1
constexpr int K2 = 128;       // clusters pool 2

// scratch offsets (floats)
constexpr size_t O_QKVS = 0;                           // [NT,512] q|k|v|skip
constexpr size_t O_HF   = O_QKVS + (size_t)NT*512;
constexpr size_t O_S1   = O_HF   + (size_t)NT*Hh;
constexpr size_t O_S1T  = O_S1   + (size_t)NT*K1;      // [Bn][K1][Nn]
constexpr size_t O_T1   = O_S1T  + (size_t)NT*K1;
constexpr size_t O_OX1  = O_T1   + (size_t)NT*K1;
constexpr size_t O_OA1  = O_OX1  + (size_t)Bn*K1*Hh;
constexpr size_t O_D1   = O_OA1  + (size_t)Bn*K1*K1;
constexpr size_t O_AX1  = O_D1   + (size_t)Bn*K1;
constexpr size_t O_XD2  = O_AX1  + (size_t)Bn*K1*Hh;
constexpr size_t O_S2   = O_XD2  + (size_t)Bn*K1*Hh;
constexpr size_t O_S2T  = O_S2   + (size_t)Bn*K1*K2;   // [Bn][K2][K1]
constexpr size_t O_T2   = O_S2T  + (size_t)Bn*K1*K2;
constexpr size_t O_OX2  = O_T2   + (size_t)Bn*K1*K2;
constexpr size_t O_OA2  = O_OX2  + (size_t)Bn*K2*Hh;
constexpr size_t O_D2   = O_OA2  + (size_t)Bn*K2*K2;
constexpr size_t O_AX2  = O_D2   + (size_t)Bn*K2;
constexpr size_t O_XD3  = O_AX2  + (size_t)Bn*K2*Hh;
constexpr size_t O_G    = O_XD3  + (size_t)Bn*K2*Hh;
constexpr size_t O_G1   = O_G    + (size_t)Bn*Hh;
constexpr size_t O_SUM  = O_G1   + (size_t)Bn*Hh;      // bn sums -> scale
constexpr size_t O_SSQ  = O_SUM  + (size_t)Cc;         // bn ssq  -> shift
constexpr size_t O_WCAT = O_SSQ  + (size_t)Cc;
constexpr size_t O_BCAT = O_WCAT + (size_t)Cc*512;
constexpr size_t O_INT  = O_BCAT + 512;

// int offsets (in ints, relative to O_INT)
constexpr size_t I_ADJ  = 0;                 // dstsBySrc [Ee]
constexpr size_t I_PAIR = I_ADJ  + Ee;       // int2 pairs by dst [Ee]
constexpr size_t I_CNT  = I_PAIR + 2*(size_t)Ee;   // cntS|cntD [2NT]
constexpr size_t I_OFFS = I_CNT  + 2*(size_t)NT;
constexpr size_t I_OFFD = I_OFFS + NT + 1;
constexpr size_t I_CURS = I_OFFD + NT + 1;
constexpr size_t I_CURD = I_CURS + NT;
constexpr size_t I_AUX  = I_CURD + NT;
constexpr size_t I_END  = I_AUX  + 256;

constexpr size_t TOTALF = O_INT + I_END + 64;
} // namespace

__device__ float GBUF[TOTALF];

// ---------------------------------------------------------------------------
// Setup: wcat + zero counters + zero bn accumulators (one launch)
// ---------------------------------------------------------------------------
__global__ void setup_kernel(const float* __restrict__ Wq, const float* __restrict__ Wk,
                             const float* __restrict__ Wv, const float* __restrict__ Ws,
                             const float* __restrict__ bq, const float* __restrict__ bk,
                             const float* __restrict__ bv, const float* __restrict__ bs,
                             float* __restrict__ Wcat, float* __restrict__ bcat,
                             int* __restrict__ cnt, float* __restrict__ sums) {
    int idx = blockIdx.x * blockDim.x + threadIdx.x; // 65536 threads
    if (idx < Cc * 512) {
        int k = idx >> 9, j = idx & 511;
        int sel = j >> 7, jj = j & 127;
        const float* W = sel == 0 ? Wq : sel == 1 ? Wk : sel == 2 ? Wv : Ws;
        Wcat[idx] = W[k * Hh + jj];
        if (k == 0) {
            const float* b = sel == 0 ? bq : sel == 1 ? bk : sel == 2 ? bv : bs;
            bcat[j] = b[jj];
        }
        cnt[idx] = 0;                    // 2*NT == 65536
        if (idx < 2 * Cc) sums[idx] = 0.f;
    }
}

// ---------------------------------------------------------------------------
// BatchNorm: reduce, then stats -> scale/shift (in place over sum/ssq)
// ---------------------------------------------------------------------------
__global__ void bn_reduce_kernel(const float* __restrict__ x, float* __restrict__ sum,
                                 float* __restrict__ ssq) {
    int c = threadIdx.x;
    float s = 0.f, ss = 0.f;
    for (int r = blockIdx.x; r < NT; r += gridDim.x) {
        float v = x[(size_t)r * Cc + c];
        s += v; ss += v * v;
    }
    atomicAdd(&sum[c], s);
    atomicAdd(&ssq[c], ss);
}

__global__ void bn_stats_kernel(float* __restrict__ sum, float* __restrict__ ssq,
                                const float* __restrict__ gamma, const float* __restrict__ beta) {
    int c = threadIdx.x; // 128
    float mu  = sum[c] * (1.f / NT);
    float var = ssq[c] * (1.f / NT) - mu * mu;
    float sc  = gamma[c] * rsqrtf(var + 1e-5f);
    sum[c] = sc;                     // scale
    ssq[c] = beta[c] - mu * sc;      // shift
}

// ---------------------------------------------------------------------------
// Pipelined pre-split 3xTF32 tensor-core GEMM:
//   C = act((A*as+ash)*B [+ A2*B2] + bias + Cadd)
// Block tile 128x64, 8 warps (4M x 2N), warp tile 32x32.
// Software pipeline: LDG of tile k+1 issued before compute of tile k;
// split+STS after the compute barrier. Hides global-load latency.
// ---------------------------------------------------------------------------
__device__ __forceinline__ unsigned tf32_of(float v) {
    unsigned h;
    asm("cvt.rna.tf32.f32 %0, %1;" : "=r"(h) : "f"(v));
    return h;
}

__device__ __forceinline__ void mma_tf32(float4& c, unsigned a0, unsigned a1, unsigned a2,
                                         unsigned a3, unsigned b0, unsigned b1) {
    asm volatile(
        "mma.sync.aligned.m16n8k8.row.col.f32.tf32.tf32.f32 "
        "{%0,%1,%2,%3}, {%4,%5,%6,%7}, {%8,%9}, {%0,%1,%2,%3};"
        : "+f"(c.x), "+f"(c.y), "+f"(c.z), "+f"(c.w)
        : "r"(a0), "r"(a1), "r"(a2), "r"(a3), "r"(b0), "r"(b1));
}

template <int ACT, bool DUAL, bool BNA>
__global__ void __launch_bounds__(256)
gemm_tc_kernel(const float* __restrict__ A, const float* __restrict__ Bm,
               const float* __restrict__ A2, const float* __restrict__ B2,
               float* __restrict__ C, const float* __restrict__ bias,
               const float* __restrict__ Cadd,
               const float* __restrict__ ascale, const float* __restrict__ ashift,
               int M, int N, int K, int lda, int ldb, int ldc,
               long sA, long sB, long sC) {
    constexpr int BM = 128, BN = 64, BK = 16, LD = 20;
    __shared__ unsigned Ahi[BM][LD], Alo[BM][LD];
    __shared__ unsigned Bhi[BN][LD], Blo[BN][LD];

    int bz = blockIdx.z;
    const float* Cad = Cadd ? Cadd + (size_t)bz * sC : nullptr;
    C += (size_t)bz * sC;

    int m0 = blockIdx.y * BM, n0 = blockIdx.x * BN;
    int t = threadIdx.x;
    int warp = t >> 5, lane = t & 31;
    int wm = (warp & 3) * 32;
    int wn = (warp >> 2) * 32;
    int rr = lane >> 2, cc = lane & 3;

    // loader roles
    int am = t >> 1, ak8 = (t & 1) * 8;   // A: row am, 8 consecutive k
    int bk_ = t >> 4, bnb = t & 15;       // B: k row bk_, 4 n values

    const int itersPerPass = K / BK;
    const int nIter = (DUAL ? 2 : 1) * itersPerPass;

    float avv[8];
    float bvv[4];

#define LOAD_TILE(IT) {                                                          \
        int pass_ = (IT) / itersPerPass;                                         \
        int k0_ = ((IT) % itersPerPass) * BK;                                    \
        const float* Ap_ = (!DUAL || pass_ == 0) ? A + (size_t)bz * sA : A2;     \
        const float* Bp_ = (!DUAL || pass_ == 0) ? Bm + (size_t)bz * sB : B2;    \
        const float* ap_ = &Ap_[(size_t)(m0 + am) * lda + k0_ + ak8];            \
        float4 v0_ = *(const float4*)ap_;                                        \
        float4 v1_ = *(const float4*)(ap_ + 4);                                  \
        avv[0] = v0_.x; avv[1] = v0_.y; avv[2] = v0_.z; avv[3] = v0_.w;          \
        avv[4] = v1_.x; avv[5] = v1_.y; avv[6] = v1_.z; avv[7] = v1_.w;          \
        if (BNA) {                                                               \
            _Pragma("unroll")                                                    \
            for (int i_ = 0; i_ < 8; i_++)                                       \
                avv[i_] = avv[i_] * __ldg(&ascale[k0_ + ak8 + i_]) +             \
                          __ldg(&ashift[k0_ + ak8 + i_]);                        \
        }                                                                        \
        const float* brow_ = &Bp_[(size_t)(k0_ + bk_) * ldb + n0];               \
        _Pragma("unroll")                                                        \
        for (int i_ = 0; i_ < 4; i_++) bvv[i_] = brow_[bnb + 16 * i_];           \
    }

#define STORE_TILE() {                                                           \
        unsigned hi_[8], lo_[8];                                                 \
        _Pragma("unroll")                                                        \
        for (int i_ = 0; i_ < 8; i_++) {                                         \
            hi_[i_] = tf32_of(avv[i_]);                                          \
            lo_[i_] = tf32_of(avv[i_] - __uint_as_float(hi_[i_]));               \
        }                                                                        \
        *(uint4*)&Ahi[am][ak8]     = make_uint4(hi_[0], hi_[1], hi_[2], hi_[3]); \
        *(uint4*)&Ahi[am][ak8 + 4] = make_uint4(hi_[4], hi_[5], hi_[6], hi_[7]); \
        *(uint4*)&Alo[am][ak8]     = make_uint4(lo_[0], lo_[1], lo_[2], lo_[3]); \
        *(uint4*)&Alo[am][ak8 + 4] = make_uint4(lo_[4], lo_[5], lo_[6], lo_[7]); \
        _Pragma("unroll")                                                        \
        for (int i_ = 0; i_ < 4; i_++) {                                         \
            int n_ = bnb + 16 * i_;                                              \
            unsigned h_ = tf32_of(bvv[i_]);                                      \
            Bhi[n_][bk_] = h_;                                                   \
            Blo[n_][bk_] = tf32_of(bvv[i_] - __uint_as_float(h_));               \
        }                                                                        \
    }

    float4 acc[2][4];
#pragma unroll
    for (int f = 0; f < 2; f++)
#pragma unroll
        for (int g = 0; g < 4; g++) acc[f][g] = make_float4(0.f, 0.f, 0.f, 0.f);

    // prologue: tile 0 into smem
    LOAD_TILE(0);
    STORE_TILE();

    for (int it = 0; it < nIter; it++) {
        __syncthreads();                    // tile `it` visible in smem
        if (it + 1 < nIter) LOAD_TILE(it + 1);   // LDG overlaps compute below

#pragma unroll
        for (int kk = 0; kk < BK; kk += 8) {
            unsigned ah[2][4], al[2][4];
#pragma unroll
            for (int f = 0; f < 2; f++) {
                int r = wm + 16 * f + rr;
                ah[f][0] = Ahi[r][kk + cc];       ah[f][1] = Ahi[r + 8][kk + cc];
                ah[f][2] = Ahi[r][kk + cc + 4];   ah[f][3] = Ahi[r + 8][kk + cc + 4];
                al[f][0] = Alo[r][kk + cc];       al[f][1] = Alo[r + 8][kk + cc];
                al[f][2] = Alo[r][kk + cc + 4];   al[f][3] = Alo[r + 8][kk + cc + 4];
            }
            unsigned bh[4][2], bl[4][2];
#pragma unroll
            for (int g = 0; g < 4; g++) {
                int n = wn + 8 * g + rr;
                bh[g][0] = Bhi[n][kk + cc];  bh[g][1] = Bhi[n][kk + cc + 4];
                bl[g][0] = Blo[n][kk + cc];  bl[g][1] = Blo[n][kk + cc + 4];
            }
#pragma unroll
            for (int f = 0; f < 2; f++)
#pragma unroll
                for (int g = 0; g < 4; g++) {
                    mma_tf32(acc[f][g], ah[f][0], ah[f][1], ah[f][2], ah[f][3],
                             bh[g][0], bh[g][1]);
                    mma_tf32(acc[f][g], ah[f][0], ah[f][1], ah[f][2], ah[f][3],
                             bl[g][0], bl[g][1]);
                    mma_tf32(acc[f][g], al[f][0], al[f][1], al[f][2], al[f][3],
                             bh[g][0], bh[g][1]);
                }
        }
        __syncthreads();                    // all warps done reading smem
        if (it + 1 < nIter) STORE_TILE();   // overwrite smem with staged tile
    }

#undef LOAD_TILE
#undef STORE_TILE

    // --- epilogue ---
#pragma unroll
    for (int f = 0; f < 2; f++) {
#pragma unroll
        for (int g = 0; g < 4; g++) {
            int r0 = m0 + wm + 16 * f + rr;
            int c0 = n0 + wn + 8 * g + cc * 2;
            float bx = 0.f, by = 0.f;
            if (bias) { bx = bias[c0]; by = bias[c0 + 1]; }
            float2 top = make_float2(acc[f][g].x + bx, acc[f][g].y + by);
            float2 bot = make_float2(acc[f][g].z + bx, acc[f][g].w + by);
            size_t offT = (size_t)r0 * ldc + c0;
            size_t offB = (size_t)(r0 + 8) * ldc + c0;
            if (Cad) {
                float2 t0 = *(const float2*)&Cad[offT];
                float2 t1 = *(const float2*)&Cad[offB];
                top.x += t0.x; top.y += t0.y;
                bot.x += t1.x; bot.y += t1.y;
            }
            if (ACT == 1) {
                top.x = fmaxf(top.x, 0.f); top.y = fmaxf(top.y, 0.f);
                bot.x = fmaxf(bot.x, 0.f); bot.y = fmaxf(bot.y, 0.f);
            }
            *(float2*)&C[offT] = top;
            *(float2*)&C[offB] = bot;
        }
    }
}

// ---------------------------------------------------------------------------
// CSR build
// ---------------------------------------------------------------------------
__global__ void csr_count_kernel(const int* __restrict__ src, const int* __restrict__ dst,
                                 int* __restrict__ cnt) {
    int e = blockIdx.x * blockDim.x + threadIdx.x;
    if (e >= Ee) return;
    atomicAdd(&cnt[src[e]], 1);
    atomicAdd(&cnt[NT + dst[e]], 1);
}

__global__ void scan_chunk_kernel(const int* __restrict__ cnt, int* __restrict__ excl,
                                  int* __restrict__ aux) {
    __shared__ int sm[256];
    int c = blockIdx.x, t = threadIdx.x;
    int v = cnt[c * 256 + t];
    sm[t] = v;
    __syncthreads();
    for (int d = 1; d < 256; d <<= 1) {
        int u = (t >= d) ? sm[t - d] : 0;
        __syncthreads();
        sm[t] += u;
        __syncthreads();
    }
    excl[c * 256 + t] = sm[t] - v;
    if (t == 255) aux[c] = sm[255];
}

__global__ void scan_aux_kernel(int* __restrict__ aux) {
    __shared__ int sm[256];
    int t = threadIdx.x;
    int i = t & 127;
    int v = aux[t];
    sm[t] = v;
    __syncthreads();
    for (int d = 1; d < 128; d <<= 1) {
        int u = (i >= d) ? sm[t - d] : 0;
        __syncthreads();
        sm[t] += u;
        __syncthreads();
    }
    aux[t] = sm[t] - v;
}

__global__ void scan_final_kernel(const int* __restrict__ excl, const int* __restrict__ aux,
                                  int* __restrict__ offS, int* __restrict__ curS,
                                  int* __restrict__ offD, int* __restrict__ curD) {
    int c = blockIdx.x, t = threadIdx.x;
    int idx = c * 256 + t;
    int v = excl[idx] + aux[c];
    if (idx < NT) { offS[idx] = v; curS[idx] = v; }
    else          { offD[idx - NT] = v; curD[idx - NT] = v; }
    if (idx == 0) { offS[NT] = Ee; offD[NT] = Ee; }
}

__global__ void csr_scatter_kernel(const int* __restrict__ src, const int* __restrict__ dst,
                                   int* __restrict__ curS, int* __restrict__ curD,
                                   int* __restrict__ dstsBySrc, int2* __restrict__ pairByDst) {
    int e = blockIdx.x * blockDim.x + threadIdx.x;
    if (e >= Ee) return;
    int s = src[e], d = dst[e];
    int ps = atomicAdd(&curS[s], 1);
    dstsBySrc[ps] = d;
    int pd = atomicAdd(&curD[d], 1);
    pairByDst[pd] = make_int2(s, e);
}

// ---------------------------------------------------------------------------
// Fused TransformerConv — vectorized: lane owns h in [lane*4, lane*4+4)
// ---------------------------------------------------------------------------
__global__ void attn_fused_kernel(const int* __restrict__ offD, const int2* __restrict__ pair,
                                  const float* __restrict__ ea, const float* __restrict__ We,
                                  const float* __restrict__ qkvs, float* __restrict__ h) {
    __shared__ float sWe[Ed * Hh];
    for (int i = threadIdx.x; i < Ed * Hh; i += blockDim.x) sWe[i] = We[i];
    __syncthreads();
    int d = blockIdx.x * (blockDim.x >> 5) + (threadIdx.x >> 5);
    int lane = threadIdx.x & 31;
    if (d >= NT) return;

    float4 qv  = *(const float4*)&qkvs[(size_t)d * 512 + lane * 4];
    float4 we0 = *(const float4*)&sWe[0 * Hh + lane * 4];
    float4 we1 = *(const float4*)&sWe[1 * Hh + lane * 4];
    float4 we2 = *(const float4*)&sWe[2 * Hh + lane * 4];
    float4 we3 = *(const float4*)&sWe[3 * Hh + lane * 4];
    float4 we4 = *(const float4*)&sWe[4 * Hh + lane * 4];

    float m = -1e30f, ssum = 0.f;
    float4 acc = make_float4(0.f, 0.f, 0.f, 0.f);

    int beg = offD[d], end = offD[d + 1];
    for (int i = beg; i < end; i++) {
        int2 p = pair[i];
        const float* eap = ea + (size_t)p.y * 5;
        float a0 = eap[0], a1 = eap[1], a2 = eap[2], a3 = eap[3], a4 = eap[4];
        float4 ev;
        ev.x = a0 * we0.x + a1 * we1.x + a2 * we2.x + a3 * we3.x + a4 * we4.x;
        ev.y = a0 * we0.y + a1 * we1.y + a2 * we2.y + a3 * we3.y + a4 * we4.y;
        ev.z = a0 * we0.z + a1 * we1.z + a2 * we2.z + a3 * we3.z + a4 * we4.z;
        ev.w = a0 * we0.w + a1 * we1.w + a2 * we2.w + a3 * we3.w + a4 * we4.w;
        const float4 kv = *(const float4*)&qkvs[(size_t)p.x * 512 + 128 + lane * 4];
        const float4 vv = *(const float4*)&qkvs[(size_t)p.x * 512 + 256 + lane * 4];
        float dot = qv.x * (kv.x + ev.x) + qv.y * (kv.y + ev.y) +
                    qv.z * (kv.z + ev.z) + qv.w * (kv.w + ev.w);
#pragma unroll
        for (int o = 16; o > 0; o >>= 1) dot += __shfl_xor_sync(0xffffffffu, dot, o);
        float lg = dot * 0.08838834764831845f;
        float mn = fmaxf(m, lg);
        float sc = __expf(m - mn);
        float pw = __expf(lg - mn);
        ssum = ssum * sc + pw;
        acc.x = acc.x * sc + pw * (vv.x + ev.x);
        acc.y = acc.y * sc + pw * (vv.y + ev.y);
        acc.z = acc.z * sc + pw * (vv.z + ev.z);
        acc.w = acc.w * sc + pw * (vv.w + ev.w);
        m = mn;
    }
    float inv = (ssum > 0.f) ? 1.f / ssum : 0.f;
    float4 skip = *(const float4*)&qkvs[(size_t)d * 512 + 384 + lane * 4];
    float4 o;
    o.x = fmaxf(acc.x * inv + skip.x, 0.f);
    o.y = fmaxf(acc.y * inv + skip.y, 0.f);
    o.z = fmaxf(acc.z * inv + skip.z, 0.f);
    o.w = fmaxf(acc.w * inv + skip.w, 0.f);
    *(float4*)&h[(size_t)d * Hh + lane * 4] = o;
}

// ---------------------------------------------------------------------------
// T1 = adj @ s1 via CSR gather — vectorized float4
// ---------------------------------------------------------------------------
__global__ void t1_gather_kernel(const int* __restrict__ offS, const int* __restrict__ dstsBySrc,
                                 const float* __restrict__ s1, float* __restrict__ T1) {
    int s = blockIdx.x * (blockDim.x >> 5) + (threadIdx.x >> 5);
    int lane = threadIdx.x & 31;
    if (s >= NT) return;
    float4 a0 = make_float4(0.f, 0.f, 0.f, 0.f);
    float4 a1 = make_float4(0.f, 0.f, 0.f, 0.f);
    int beg = offS[s], end = offS[s + 1];
    for (int i = beg; i < end; i++) {
        const float4* row = (const float4*)(s1 + (size_t)dstsBySrc[i] * K1);
        float4 r0 = row[lane], r1 = row[lane + 32];
        a0.x += r0.x; a0.y += r0.y; a0.z += r0.z; a0.w += r0.w;
        a1.x += r1.x; a1.y += r1.y; a1.z += r1.z; a1.w += r1.w;
    }
    float4* trow = (float4*)(T1 + (size_t)s * K1);
    trow[lane] = a0;
    trow[lane + 32] = a1;
}

// ---------------------------------------------------------------------------
// Per-graph tiled transpose
// ---------------------------------------------------------------------------
__global__ void transpose_pg_kernel(const float* __restrict__ in, float* __restrict__ outp,
                                    int R, int Cq) {
    __shared__ float tile[32][33];
    int b = blockIdx.z;
    int c0 = blockIdx.x * 32, r0 = blockIdx.y * 32;
    int tx = threadIdx.x, ty = threadIdx.y;
    const float* ip = in + (size_t)b * R * Cq;
    float* op = outp + (size_t)b * R * Cq;
#pragma unroll
    for (int i = 0; i < 32; i += 8)
        tile[ty + i][tx] = ip[(size_t)(r0 + ty + i) * Cq + c0 + tx];
    __syncthreads();
#pragma unroll
    for (int i = 0; i < 32; i += 8)
        op[(size_t)(c0 + ty + i) * R + r0 + tx] = tile[tx][ty + i];
}

// ---------------------------------------------------------------------------
// small FFMA GEMM for readout
// ---------------------------------------------------------------------------
template <int ACT>
__global__ void gemm64_kernel(const float* __restrict__ A, const float* __restrict__ Bm,
                              float* __restrict__ C, const float* __restrict__ bias,
                              int M, int N, int K, int lda, int ldb, int ldc) {
    constexpr int BM = 64, BN = 64, BK = 16;
    __shared__ float As[BK][BM + 1];
    __shared__ float Bs[BK][BN];
    int m0 = blockIdx.y * BM, n0 = blockIdx.x * BN;
    int t = threadIdx.x;
    int tx = t & 15, ty = t >> 4;
    float acc[4][4] = {};
    for (int k0 = 0; k0 < K; k0 += BK) {
        {
            int mm = t >> 2, kk = (t & 3) << 2;
            const float4 av = *(const float4*)&A[(size_t)(m0 + mm) * lda + k0 + kk];
            As[kk + 0][mm] = av.x; As[kk + 1][mm] = av.y;
            As[kk + 2][mm] = av.z; As[kk + 3][mm] = av.w;
        }
        {
            int kk = t >> 4, nn = (t & 15) << 2;
            *(float4*)&Bs[kk][nn] = *(const float4*)&Bm[(size_t)(k0 + kk) * ldb + n0 + nn];
        }
        __syncthreads();
#pragma unroll
        for (int kk = 0; kk < BK; kk++) {
            float a0 = As[kk][ty * 4 + 0], a1 = As[kk][ty * 4 + 1];
            float a2 = As[kk][ty * 4 + 2], a3 = As[kk][ty * 4 + 3];
            float4 b = *(const float4*)&Bs[kk][tx * 4];
            acc[0][0] += a0 * b.x; acc[0][1] += a0 * b.y; acc[0][2] += a0 * b.z; acc[0][3] += a0 * b.w;
            acc[1][0] += a1 * b.x; acc[1][1] += a1 * b.y; acc[1][2] += a1 * b.z; acc[1][3] += a1 * b.w;
            acc[2][0] += a2 * b.x; acc[2][1] += a2 * b.y; acc[2][2] += a2 * b.z; acc[2][3] += a2 * b.w;
            acc[3][0] += a3 * b.x; acc[3][1] += a3 * b.y; acc[3][2] += a3 * b.z; acc[3][3] += a3 * b.w;
        }
        __syncthreads();
    }
#pragma unroll
    for (int i = 0; i < 4; i++) {
        int m = m0 + ty * 4 + i;
        size_t off = (size_t)m * ldc + n0 + tx * 4;
        float4 r = make_float4(acc[i][0], acc[i][1], acc[i][2], acc[i][3]);
        if (bias) {
            int nb = n0 + tx * 4;
            r.x += bias[nb + 0]; r.y += bias[nb + 1];
            r.z += bias[nb + 2]; r.w += bias[nb + 3];
        }
        if (ACT == 1) {
            r.x = fmaxf(r.x, 0.f); r.y = fmaxf(r.y, 0.f);
            r.z = fmaxf(r.z, 0.f); r.w = fmaxf(r.w, 0.f);
        }
        *(float4*)&C[off] = r;
    }
}

// ---------------------------------------------------------------------------
// Softmax over rows
// ---------------------------------------------------------------------------
__global__ void softmax_rows_kernel(float* __restrict__ X, int rows, int cols) {
    int row = blockIdx.x * (blockDim.x >> 5) + (threadIdx.x >> 5);
    int lane = threadIdx.x & 31;
    if (row >= rows) return;
    float* p = X + (size_t)row * cols;
    float mx = -1e30f;
    for (int c = lane; c < cols; c += 32) mx = fmaxf(mx, p[c]);
#pragma unroll
    for (int o = 16; o > 0; o >>= 1) mx = fmaxf(mx, __shfl_xor_sync(0xffffffffu, mx, o));
    float sum = 0.f;
    for (int c = lane; c < cols; c += 32) {
        float v = __expf(p[c] - mx);
        p[c] = v;
        sum += v;
    }
#pragma unroll
    for (int o = 16; o > 0; o >>= 1) sum += __shfl_xor_sync(0xffffffffu, sum, o);
    float inv = 1.f / sum;
    for (int c = lane; c < cols; c += 32) p[c] *= inv;
}

// ---------------------------------------------------------------------------
// out_adj normalization
// ---------------------------------------------------------------------------
__global__ void adj_rowsum_kernel(float* __restrict__ A, float* __restrict__ d, int Kd) {
    int b = blockIdx.y, i = blockIdx.x, tid = threadIdx.x;
    float* row = A + ((size_t)b * Kd + i) * Kd;
    float v = row[tid];
    if (tid == i) { v = 0.f; row[tid] = 0.f; }
    __shared__ float sh[256];
    sh[tid] = v;
    __syncthreads();
    for (int s = Kd >> 1; s > 0; s >>= 1) {
        if (tid < s) sh[tid] += sh[tid + s];
        __syncthreads();
    }
    if (tid == 0) d[(size_t)b * Kd + i] = sqrtf(sh[0]) + 1e-15f;
}

__global__ void adj_divide_kernel(float* __restrict__ A, const float* __restrict__ d, int Kd,
                                  size_t total) {
    size_t i = (size_t)blockIdx.x * blockDim.x + threadIdx.x;
    if (i >= total) return;
    int j = (int)(i % Kd);
    size_t bi = i / Kd;
    int ii = (int)(bi % Kd);
    int b = (int)(bi / Kd);
    A[i] = A[i] / (d[(size_t)b * Kd + ii] * d[(size_t)b * Kd + j]);
}

// ---------------------------------------------------------------------------
// Readout
// ---------------------------------------------------------------------------
__global__ void mean_nodes_kernel(const float* __restrict__ xd, float* __restrict__ g) {
    int b = blockIdx.x, f = threadIdx.x;
    float s = 0.f;
    for (int n = 0; n < K2; n++) s += xd[((size_t)b * K2 + n) * Hh + f];
    g[(size_t)b * Hh + f] = s * (1.f / K2);
}

__global__ void readout_kernel(const float* __restrict__ g1, const float* __restrict__ Wro,
                               const float* __restrict__ bro, float* __restrict__ out) {
    int b = blockIdx.x, lane = threadIdx.x;
    float s = 0.f;
    for (int j = lane; j < Hh; j += 32) s += g1[(size_t)b * Hh + j] * Wro[j];
#pragma unroll
    for (int o = 16; o > 0; o >>= 1) s += __shfl_xor_sync(0xffffffffu, s, o);
    if (lane == 0) out[b] = 1.f / (1.f + expf(-(s + bro[0])));
}

// ---------------------------------------------------------------------------
// Host side
// ---------------------------------------------------------------------------
static void launch_gemm(int act, const float* A, const float* B, float* C,
                        const float* bias, const float* Cadd, int M, int N, int K, int lda,
                        int ldb, int ldc, long sA, long sB, long sC, int batch) {
    dim3 grid(N / 64, M / 128, batch), block(256);
    if (act == 1) {
        gemm_tc_kernel<1, false, false><<<grid, block>>>(A, B, nullptr, nullptr, C, bias, Cadd,
                                                         nullptr, nullptr,
                                                         M, N, K, lda, ldb, ldc, sA, sB, sC);
    } else {
        gemm_tc_kernel<0, false, false><<<grid, block>>>(A, B, nullptr, nullptr, C, bias, Cadd,
                                                         nullptr, nullptr,
                                                         M, N, K, lda, ldb, ldc, sA, sB, sC);
    }
}

static void launch_gemm_dual(int act, const float* A, const float* B, const float* A2,
                             const float* B2, float* C, const float* bias, int M, int N, int K,
                             int ld) {
    dim3 grid(N / 64, M / 128, 1), block(256);
    if (act == 1) {
        gemm_tc_kernel<1, true, false><<<grid, block>>>(A, B, A2, B2, C, bias, nullptr,
                                                        nullptr, nullptr,
                                                        M, N, K, ld, N, N, 0, 0, 0);
    } else {
        gemm_tc_kernel<0, true, false><<<grid, block>>>(A, B, A2, B2, C, bias, nullptr,
                                                        nullptr, nullptr,
                                                        M, N, K, ld, N, N, 0, 0, 0);
    }
}

extern "C" void kernel_launch(void* const* d_in, const int* in_sizes, int n_in,
                              void* d_out, int out_size) {
    const float* x      = (const float*)d_in[0];
    const int*   ei     = (const int*)d_in[1];
    const float* ea     = (const float*)d_in[2];
    const float* bng    = (const float*)d_in[4];
    const float* bnb    = (const float*)d_in[5];
    const float* Wq     = (const float*)d_in[6];
    const float* bq     = (const float*)d_in[7];
    const float* Wk     = (const float*)d_in[8];
    const float* bk     = (const float*)d_in[9];
    const float* Wv     = (const float*)d_in[10];
    const float* bv     = (const float*)d_in[11];
    const float* We     = (const float*)d_in[12];
    const float* Wskip  = (const float*)d_in[13];
    const float* bskip  = (const float*)d_in[14];
    const float* Wm1    = (const float*)d_in[15];
    const float* bm1    = (const float*)d_in[16];
    const float* W2rel  = (const float*)d_in[17];
    const float* b2rel  = (const float*)d_in[18];
    const float* W2root = (const float*)d_in[19];
    const float* Wm2    = (const float*)d_in[20];
    const float* bm2    = (const float*)d_in[21];
    const float* W3rel  = (const float*)d_in[22];
    const float* b3rel  = (const float*)d_in[23];
    const float* W3root = (const float*)d_in[24];
    const float* Wlin1  = (const float*)d_in[25];
    const float* blin1  = (const float*)d_in[26];
    const float* Wro    = (const float*)d_in[27];
    const float* bro    = (const float*)d_in[28];
    float* out = (float*)d_out;

    const int* src = ei;
    const int* dst = ei + Ee;

    float* gb = nullptr;
    cudaGetSymbolAddress((void**)&gb, GBUF);
    int* ib = (int*)(gb + O_INT);

    int*  cnt  = ib + I_CNT;
    int*  offS = ib + I_OFFS;
    int*  offD = ib + I_OFFD;
    int*  curS = ib + I_CURS;
    int*  curD = ib + I_CURD;
    int*  aux  = ib + I_AUX;
    int*  adjS = ib + I_ADJ;
    int2* pair = (int2*)(ib + I_PAIR);

    // launch 1: setup (wcat + zero cnt + zero bn sums)
    setup_kernel<<<(Cc * 512) / 256, 256>>>(Wq, Wk, Wv, Wskip, bq, bk, bv, bskip,
                                            gb + O_WCAT, gb + O_BCAT, cnt, gb + O_SUM);
    // launch 2-3: BatchNorm stats
    bn_reduce_kernel<<<256, Cc>>>(x, gb + O_SUM, gb + O_SSQ);
    bn_stats_kernel<<<1, Cc>>>(gb + O_SUM, gb + O_SSQ, bng, bnb);
    // launch 4: qkvs GEMM with fused BN prologue (PROFILED under -s 5 -c 1)
    {
        dim3 grid(512 / 64, NT / 128, 1), block(256);
        gemm_tc_kernel<0, false, true><<<grid, block>>>(
            x, gb + O_WCAT, nullptr, nullptr, gb + O_QKVS, gb + O_BCAT, nullptr,
            gb + O_SUM, gb + O_SSQ, NT, 512, Cc, Cc, 512, 512, 0, 0, 0);
    }

    // ---- CSR build ----
    csr_count_kernel<<<Ee / 256, 256>>>(src, dst, cnt);
    scan_chunk_kernel<<<256, 256>>>(cnt, ib + I_CURS, aux);
    scan_aux_kernel<<<1, 256>>>(aux);
    scan_final_kernel<<<256, 256>>>(ib + I_CURS, aux, offS, curS, offD, curD);
    csr_scatter_kernel<<<Ee / 256, 256>>>(src, dst, curS, curD, adjS, pair);

    // ---- fused attention ----
    attn_fused_kernel<<<NT / 8, 256>>>(offD, pair, ea, We, gb + O_QKVS, gb + O_HF);

    // ---- pool 1 ----
    launch_gemm(0, gb + O_HF, Wm1, gb + O_S1, bm1, nullptr,
                NT, K1, Hh, Hh, K1, K1, 0, 0, 0, 1);
    softmax_rows_kernel<<<NT / 8, 256>>>(gb + O_S1, NT, K1);

    {
        dim3 g(K1 / 32, Nn / 32, Bn), bdim(32, 8);
        transpose_pg_kernel<<<g, bdim>>>(gb + O_S1, gb + O_S1T, Nn, K1);
    }

    t1_gather_kernel<<<NT / 8, 256>>>(offS, adjS, gb + O_S1, gb + O_T1);

    launch_gemm(0, gb + O_S1T, gb + O_HF, gb + O_OX1, nullptr, nullptr,
                K1, Hh, Nn, Nn, Hh, Hh, (long)K1 * Nn, (long)Nn * Hh, (long)K1 * Hh, Bn);
    launch_gemm(0, gb + O_S1T, gb + O_T1, gb + O_OA1, nullptr, nullptr,
                K1, K1, Nn, Nn, K1, K1, (long)K1 * Nn, (long)Nn * K1, (long)K1 * K1, Bn);

    {
        dim3 g1(K1, Bn);
        adj_rowsum_kernel<<<g1, K1>>>(gb + O_OA1, gb + O_D1, K1);
        size_t tot = (size_t)Bn * K1 * K1;
        adj_divide_kernel<<<(int)((tot + 255) / 256), 256>>>(gb + O_OA1, gb + O_D1, K1, tot);
    }

    // ---- DenseGraphConv 2 ----
    launch_gemm(0, gb + O_OA1, gb + O_OX1, gb + O_AX1, nullptr, nullptr,
                K1, Hh, K1, K1, Hh, Hh, (long)K1 * K1, (long)K1 * Hh, (long)K1 * Hh, Bn);
    launch_gemm_dual(1, gb + O_AX1, W2rel, gb + O_OX1, W2root, gb + O_XD2, b2rel,
                     Bn * K1, Hh, Hh, Hh);

    // ---- pool 2 ----
    launch_gemm(0, gb + O_XD2, Wm2, gb + O_S2, bm2, nullptr,
                Bn * K1, K2, Hh, Hh, K2, K2, 0, 0, 0, 1);
    softmax_rows_kernel<<<(Bn * K1) / 8, 256>>>(gb + O_S2, Bn * K1, K2);

    {
        dim3 g(K2 / 32, K1 / 32, Bn), bdim(32, 8);
        transpose_pg_kernel<<<g, bdim>>>(gb + O_S2, gb + O_S2T, K1, K2);
    }

    launch_gemm(0, gb + O_S2T, gb + O_XD2, gb + O_OX2, nullptr, nullptr,
                K2, Hh, K1, K1, Hh, Hh, (long)K2 * K1, (long)K1 * Hh, (long)K2 * Hh, Bn);
    launch_gemm(0, gb + O_OA1, gb + O_S2, gb + O_T2, nullptr, nullptr,
                K1, K2, K1, K1, K2, K2, (long)K1 * K1, (long)K1 * K2, (long)K1 * K2, Bn);
    launch_gemm(0, gb + O_S2T, gb + O_T2, gb + O_OA2, nullptr, nullptr,
                K2, K2, K1, K1, K2, K2, (long)K2 * K1, (long)K1 * K2, (long)K2 * K2, Bn);

    {
        dim3 g2(K2, Bn);
        adj_rowsum_kernel<<<g2, K2>>>(gb + O_OA2, gb + O_D2, K2);
        size_t tot = (size_t)Bn * K2 * K2;
        adj_divide_kernel<<<(int)((tot + 255) / 256), 256>>>(gb + O_OA2, gb + O_D2, K2, tot);
    }

    // ---- DenseGraphConv 3 ----
    launch_gemm(0, gb + O_OA2, gb + O_OX2, gb + O_AX2, nullptr, nullptr,
                K2, Hh, K2, K2, Hh, Hh, (long)K2 * K2, (long)K2 * Hh, (long)K2 * Hh, Bn);
    launch_gemm_dual(0, gb + O_AX2, W3rel, gb + O_OX2, W3root, gb + O_XD3, b3rel,
                     Bn * K2, Hh, Hh, Hh);

    // ---- readout ----
    mean_nodes_kernel<<<Bn, Hh>>>(gb + O_XD3, gb + O_G);
    gemm64_kernel<1><<<dim3(2, 1), 256>>>(gb + O_G, Wlin1, gb + O_G1, blin1,
                                          Bn, Hh, Hh, Hh, Hh, Hh);
    readout_kernel<<<Bn, 32>>>(gb + O_G1, Wro, bro, out);
}

// round 12
// speedup vs baseline: 1.1534x; 1.1499x over previous
#include <cuda_runtime.h>
#include <cuda_bf16.h>
#include <math.h>

// ---------------------------------------------------------------------------
// Problem constants
// ---------------------------------------------------------------------------
namespace {
constexpr int Bn = 64;        // graphs
constexpr int Nn = 512;       // nodes per graph
constexpr int Cc = 128;       // input channels
constexpr int Hh = 128;       // hidden
constexpr int Ed = 5;         // edge dim
constexpr int Ee = 524288;    // edges
constexpr int NT = 32768;     // total nodes
constexpr int K1 = 256;       // clusters pool 1
constexpr int K2 = 128;       // clusters pool 2

// scratch offsets (floats)
constexpr size_t O_QKVS = 0;                           // [NT,512] q|k|v|skip
constexpr size_t O_HF   = O_QKVS + (size_t)NT*512;
constexpr size_t O_S1   = O_HF   + (size_t)NT*Hh;
constexpr size_t O_S1T  = O_S1   + (size_t)NT*K1;      // [Bn][K1][Nn]
constexpr size_t O_T1   = O_S1T  + (size_t)NT*K1;
constexpr size_t O_OX1  = O_T1   + (size_t)NT*K1;
constexpr size_t O_OA1  = O_OX1  + (size_t)Bn*K1*Hh;
constexpr size_t O_D1   = O_OA1  + (size_t)Bn*K1*K1;
constexpr size_t O_AX1  = O_D1   + (size_t)Bn*K1;
constexpr size_t O_XD2  = O_AX1  + (size_t)Bn*K1*Hh;
constexpr size_t O_S2   = O_XD2  + (size_t)Bn*K1*Hh;
constexpr size_t O_S2T  = O_S2   + (size_t)Bn*K1*K2;   // [Bn][K2][K1]
constexpr size_t O_T2   = O_S2T  + (size_t)Bn*K1*K2;
constexpr size_t O_OX2  = O_T2   + (size_t)Bn*K1*K2;
constexpr size_t O_OA2  = O_OX2  + (size_t)Bn*K2*Hh;
constexpr size_t O_D2   = O_OA2  + (size_t)Bn*K2*K2;
constexpr size_t O_AX2  = O_D2   + (size_t)Bn*K2;
constexpr size_t O_XD3  = O_AX2  + (size_t)Bn*K2*Hh;
constexpr size_t O_G    = O_XD3  + (size_t)Bn*K2*Hh;
constexpr size_t O_G1   = O_G    + (size_t)Bn*Hh;
constexpr size_t O_SUM  = O_G1   + (size_t)Bn*Hh;      // bn sums -> scale
constexpr size_t O_SSQ  = O_SUM  + (size_t)Cc;         // bn ssq  -> shift
constexpr size_t O_WCAT = O_SSQ  + (size_t)Cc;
constexpr size_t O_BCAT = O_WCAT + (size_t)Cc*512;
constexpr size_t O_INT  = O_BCAT + 512;

// int offsets (in ints, relative to O_INT)
constexpr size_t I_ADJ  = 0;                 // dstsBySrc [Ee]
constexpr size_t I_PAIR = I_ADJ  + Ee;       // int2 pairs by dst [Ee]
constexpr size_t I_CNT  = I_PAIR + 2*(size_t)Ee;   // cntS|cntD [2NT]
constexpr size_t I_OFFS = I_CNT  + 2*(size_t)NT;
constexpr size_t I_OFFD = I_OFFS + NT + 1;
constexpr size_t I_CURS = I_OFFD + NT + 1;
constexpr size_t I_CURD = I_CURS + NT;
constexpr size_t I_AUX  = I_CURD + NT;
constexpr size_t I_END  = I_AUX  + 256;

constexpr size_t TOTALF = O_INT + I_END + 64;
} // namespace

__device__ float GBUF[TOTALF];

// ---------------------------------------------------------------------------
// Setup: wcat + zero counters + zero bn accumulators (one launch)
// ---------------------------------------------------------------------------
__global__ void setup_kernel(const float* __restrict__ Wq, const float* __restrict__ Wk,
                             const float* __restrict__ Wv, const float* __restrict__ Ws,
                             const float* __restrict__ bq, const float* __restrict__ bk,
                             const float* __restrict__ bv, const float* __restrict__ bs,
                             float* __restrict__ Wcat, float* __restrict__ bcat,
                             int* __restrict__ cnt, float* __restrict__ sums) {
    int idx = blockIdx.x * blockDim.x + threadIdx.x; // 65536 threads
    if (idx < Cc * 512) {
        int k = idx >> 9, j = idx & 511;
        int sel = j >> 7, jj = j & 127;
        const float* W = sel == 0 ? Wq : sel == 1 ? Wk : sel == 2 ? Wv : Ws;
        Wcat[idx] = W[k * Hh + jj];
        if (k == 0) {
            const float* b = sel == 0 ? bq : sel == 1 ? bk : sel == 2 ? bv : bs;
            bcat[j] = b[jj];
        }
        cnt[idx] = 0;                    // 2*NT == 65536
        if (idx < 2 * Cc) sums[idx] = 0.f;
    }
}

// ---------------------------------------------------------------------------
// BatchNorm: reduce, then stats -> scale/shift (in place over sum/ssq)
// ---------------------------------------------------------------------------
__global__ void bn_reduce_kernel(const float* __restrict__ x, float* __restrict__ sum,
                                 float* __restrict__ ssq) {
    int c = threadIdx.x;
    float s = 0.f, ss = 0.f;
    for (int r = blockIdx.x; r < NT; r += gridDim.x) {
        float v = x[(size_t)r * Cc + c];
        s += v; ss += v * v;
    }
    atomicAdd(&sum[c], s);
    atomicAdd(&ssq[c], ss);
}

__global__ void bn_stats_kernel(float* __restrict__ sum, float* __restrict__ ssq,
                                const float* __restrict__ gamma, const float* __restrict__ beta) {
    int c = threadIdx.x; // 128
    float mu  = sum[c] * (1.f / NT);
    float var = ssq[c] * (1.f / NT) - mu * mu;
    float sc  = gamma[c] * rsqrtf(var + 1e-5f);
    sum[c] = sc;                     // scale
    ssq[c] = beta[c] - mu * sc;      // shift
}

// ---------------------------------------------------------------------------
// 3x-BF16-split tensor-core GEMM (m16n8k16), packed-u32 smem:
//   C = act((A*as+ash)*B [+ A2*B2] + bias + Cadd)
// Block tile 128x64, 8 warps (4M x 2N), warp tile 32x32.
// A smem [m][kpair] LD=12 words (conflict-free loads+stores).
// B smem [kpair][n] LD=72 words (conflict-free reads).
// ---------------------------------------------------------------------------
__device__ __forceinline__ void split2_bf(float x, float y, unsigned& h, unsigned& l) {
    __nv_bfloat16 hx = __float2bfloat16(x), hy = __float2bfloat16(y);
    __nv_bfloat16 lx = __float2bfloat16(x - __bfloat162float(hx));
    __nv_bfloat16 ly = __float2bfloat16(y - __bfloat162float(hy));
    h = ((unsigned)__bfloat16_as_ushort(hy) << 16) | (unsigned)__bfloat16_as_ushort(hx);
    l = ((unsigned)__bfloat16_as_ushort(ly) << 16) | (unsigned)__bfloat16_as_ushort(lx);
}

__device__ __forceinline__ void mma_bf16(float4& c, unsigned a0, unsigned a1, unsigned a2,
                                         unsigned a3, unsigned b0, unsigned b1) {
    asm volatile(
        "mma.sync.aligned.m16n8k16.row.col.f32.bf16.bf16.f32 "
        "{%0,%1,%2,%3}, {%4,%5,%6,%7}, {%8,%9}, {%0,%1,%2,%3};"
        : "+f"(c.x), "+f"(c.y), "+f"(c.z), "+f"(c.w)
        : "r"(a0), "r"(a1), "r"(a2), "r"(a3), "r"(b0), "r"(b1));
}

template <int ACT, bool DUAL, bool BNA>
__global__ void __launch_bounds__(256)
gemm_tc_kernel(const float* __restrict__ A, const float* __restrict__ Bm,
               const float* __restrict__ A2, const float* __restrict__ B2,
               float* __restrict__ C, const float* __restrict__ bias,
               const float* __restrict__ Cadd,
               const float* __restrict__ ascale, const float* __restrict__ ashift,
               int M, int N, int K, int lda, int ldb, int ldc,
               long sA, long sB, long sC) {
    constexpr int BM = 128, BN = 64, BK = 16;
    constexpr int LDA_ = 12;   // u32 words per A row (8 used + pad)
    constexpr int LDB_ = 72;   // u32 words per B kpair row (64 used + pad)
    __shared__ unsigned Ahi[BM][LDA_], Alo[BM][LDA_];
    __shared__ unsigned Bhi[8][LDB_], Blo[8][LDB_];

    int bz = blockIdx.z;
    const float* Cad = Cadd ? Cadd + (size_t)bz * sC : nullptr;
    C += (size_t)bz * sC;

    int m0 = blockIdx.y * BM, n0 = blockIdx.x * BN;
    int t = threadIdx.x;
    int warp = t >> 5, lane = t & 31;
    int wm = (warp & 3) * 32;
    int wn = (warp >> 2) * 32;
    int rr = lane >> 2, cc = lane & 3;

    // loader roles
    int am = t >> 1, ak8 = (t & 1) * 8;   // A: row am, k8 = 0 or 8
    int bkp = t >> 5, bl = t & 31;        // B: kpair row (0..7), lane covers n = 2*bl, 2*bl+1

    float4 acc[2][4];
#pragma unroll
    for (int f = 0; f < 2; f++)
#pragma unroll
        for (int g = 0; g < 4; g++) acc[f][g] = make_float4(0.f, 0.f, 0.f, 0.f);

    for (int pass = 0; pass < (DUAL ? 2 : 1); pass++) {
        const float* Ap = (pass == 0) ? A + (size_t)bz * sA : A2;
        const float* Bp = (pass == 0) ? Bm + (size_t)bz * sB : B2;

        for (int k0 = 0; k0 < K; k0 += BK) {
            // --- A tile: 8 consecutive k of row am -> split+pack -> uint4 x2 ---
            {
                const float* ap = &Ap[(size_t)(m0 + am) * lda + k0 + ak8];
                float4 v0 = *(const float4*)ap;
                float4 v1 = *(const float4*)(ap + 4);
                float vv[8] = {v0.x, v0.y, v0.z, v0.w, v1.x, v1.y, v1.z, v1.w};
                if (BNA) {
#pragma unroll
                    for (int i = 0; i < 8; i++)
                        vv[i] = vv[i] * __ldg(&ascale[k0 + ak8 + i]) + __ldg(&ashift[k0 + ak8 + i]);
                }
                unsigned hp[4], lp[4];
#pragma unroll
                for (int i = 0; i < 4; i++)
                    split2_bf(vv[2 * i], vv[2 * i + 1], hp[i], lp[i]);
                int kp0 = (t & 1) * 4;
                *(uint4*)&Ahi[am][kp0] = make_uint4(hp[0], hp[1], hp[2], hp[3]);
                *(uint4*)&Alo[am][kp0] = make_uint4(lp[0], lp[1], lp[2], lp[3]);
            }
            // --- B tile: [K,N] row-major; pack k-pairs per n ---
            {
                const float* br0 = &Bp[(size_t)(k0 + 2 * bkp) * ldb + n0 + 2 * bl];
                float2 x0 = *(const float2*)br0;
                float2 x1 = *(const float2*)(br0 + ldb);
                unsigned h0, l0, h1, l1;
                split2_bf(x0.x, x1.x, h0, l0);   // n = 2*bl : (k even, k odd)
                split2_bf(x0.y, x1.y, h1, l1);   // n = 2*bl+1
                int nn = 2 * bl;
                Bhi[bkp][nn] = h0; Bhi[bkp][nn + 1] = h1;
                Blo[bkp][nn] = l0; Blo[bkp][nn + 1] = l1;
            }
            __syncthreads();

            // --- fragments + 3-term MMA (one k16 step per tile) ---
            unsigned ah[2][4], al[2][4];
#pragma unroll
            for (int f = 0; f < 2; f++) {
                int r = wm + 16 * f + rr;
                ah[f][0] = Ahi[r][cc];       ah[f][1] = Ahi[r + 8][cc];
                ah[f][2] = Ahi[r][cc + 4];   ah[f][3] = Ahi[r + 8][cc + 4];
                al[f][0] = Alo[r][cc];       al[f][1] = Alo[r + 8][cc];
                al[f][2] = Alo[r][cc + 4];   al[f][3] = Alo[r + 8][cc + 4];
            }
            unsigned bh[4][2], blv[4][2];
#pragma unroll
            for (int g = 0; g < 4; g++) {
                int n = wn + 8 * g + rr;
                bh[g][0]  = Bhi[cc][n];      bh[g][1]  = Bhi[cc + 4][n];
                blv[g][0] = Blo[cc][n];      blv[g][1] = Blo[cc + 4][n];
            }
#pragma unroll
            for (int f = 0; f < 2; f++)
#pragma unroll
                for (int g = 0; g < 4; g++) {
                    mma_bf16(acc[f][g], ah[f][0], ah[f][1], ah[f][2], ah[f][3],
                             bh[g][0], bh[g][1]);
                    mma_bf16(acc[f][g], ah[f][0], ah[f][1], ah[f][2], ah[f][3],
                             blv[g][0], blv[g][1]);
                    mma_bf16(acc[f][g], al[f][0], al[f][1], al[f][2], al[f][3],
                             bh[g][0], bh[g][1]);
                }
            __syncthreads();
        }
    }

    // --- epilogue ---
#pragma unroll
    for (int f = 0; f < 2; f++) {
#pragma unroll
        for (int g = 0; g < 4; g++) {
            int r0 = m0 + wm + 16 * f + rr;
            int c0 = n0 + wn + 8 * g + cc * 2;
            float bx = 0.f, by = 0.f;
            if (bias) { bx = bias[c0]; by = bias[c0 + 1]; }
            float2 top = make_float2(acc[f][g].x + bx, acc[f][g].y + by);
            float2 bot = make_float2(acc[f][g].z + bx, acc[f][g].w + by);
            size_t offT = (size_t)r0 * ldc + c0;
            size_t offB = (size_t)(r0 + 8) * ldc + c0;
            if (Cad) {
                float2 t0 = *(const float2*)&Cad[offT];
                float2 t1 = *(const float2*)&Cad[offB];
                top.x += t0.x; top.y += t0.y;
                bot.x += t1.x; bot.y += t1.y;
            }
            if (ACT == 1) {
                top.x = fmaxf(top.x, 0.f); top.y = fmaxf(top.y, 0.f);
                bot.x = fmaxf(bot.x, 0.f); bot.y = fmaxf(bot.y, 0.f);
            }
            *(float2*)&C[offT] = top;
            *(float2*)&C[offB] = bot;
        }
    }
}

// ---------------------------------------------------------------------------
// CSR build
// ---------------------------------------------------------------------------
__global__ void csr_count_kernel(const int* __restrict__ src, const int* __restrict__ dst,
                                 int* __restrict__ cnt) {
    int e = blockIdx.x * blockDim.x + threadIdx.x;
    if (e >= Ee) return;
    atomicAdd(&cnt[src[e]], 1);
    atomicAdd(&cnt[NT + dst[e]], 1);
}

__global__ void scan_chunk_kernel(const int* __restrict__ cnt, int* __restrict__ excl,
                                  int* __restrict__ aux) {
    __shared__ int sm[256];
    int c = blockIdx.x, t = threadIdx.x;
    int v = cnt[c * 256 + t];
    sm[t] = v;
    __syncthreads();
    for (int d = 1; d < 256; d <<= 1) {
        int u = (t >= d) ? sm[t - d] : 0;
        __syncthreads();
        sm[t] += u;
        __syncthreads();
    }
    excl[c * 256 + t] = sm[t] - v;
    if (t == 255) aux[c] = sm[255];
}

__global__ void scan_aux_kernel(int* __restrict__ aux) {
    __shared__ int sm[256];
    int t = threadIdx.x;
    int i = t & 127;
    int v = aux[t];
    sm[t] = v;
    __syncthreads();
    for (int d = 1; d < 128; d <<= 1) {
        int u = (i >= d) ? sm[t - d] : 0;
        __syncthreads();
        sm[t] += u;
        __syncthreads();
    }
    aux[t] = sm[t] - v;
}

__global__ void scan_final_kernel(const int* __restrict__ excl, const int* __restrict__ aux,
                                  int* __restrict__ offS, int* __restrict__ curS,
                                  int* __restrict__ offD, int* __restrict__ curD) {
    int c = blockIdx.x, t = threadIdx.x;
    int idx = c * 256 + t;
    int v = excl[idx] + aux[c];
    if (idx < NT) { offS[idx] = v; curS[idx] = v; }
    else          { offD[idx - NT] = v; curD[idx - NT] = v; }
    if (idx == 0) { offS[NT] = Ee; offD[NT] = Ee; }
}

__global__ void csr_scatter_kernel(const int* __restrict__ src, const int* __restrict__ dst,
                                   int* __restrict__ curS, int* __restrict__ curD,
                                   int* __restrict__ dstsBySrc, int2* __restrict__ pairByDst) {
    int e = blockIdx.x * blockDim.x + threadIdx.x;
    if (e >= Ee) return;
    int s = src[e], d = dst[e];
    int ps = atomicAdd(&curS[s], 1);
    dstsBySrc[ps] = d;
    int pd = atomicAdd(&curD[d], 1);
    pairByDst[pd] = make_int2(s, e);
}

// ---------------------------------------------------------------------------
// Fused TransformerConv — vectorized: lane owns h in [lane*4, lane*4+4)
// ---------------------------------------------------------------------------
__global__ void attn_fused_kernel(const int* __restrict__ offD, const int2* __restrict__ pair,
                                  const float* __restrict__ ea, const float* __restrict__ We,
                                  const float* __restrict__ qkvs, float* __restrict__ h) {
    __shared__ float sWe[Ed * Hh];
    for (int i = threadIdx.x; i < Ed * Hh; i += blockDim.x) sWe[i] = We[i];
    __syncthreads();
    int d = blockIdx.x * (blockDim.x >> 5) + (threadIdx.x >> 5);
    int lane = threadIdx.x & 31;
    if (d >= NT) return;

    float4 qv  = *(const float4*)&qkvs[(size_t)d * 512 + lane * 4];
    float4 we0 = *(const float4*)&sWe[0 * Hh + lane * 4];
    float4 we1 = *(const float4*)&sWe[1 * Hh + lane * 4];
    float4 we2 = *(const float4*)&sWe[2 * Hh + lane * 4];
    float4 we3 = *(const float4*)&sWe[3 * Hh + lane * 4];
    float4 we4 = *(const float4*)&sWe[4 * Hh + lane * 4];

    float m = -1e30f, ssum = 0.f;
    float4 acc = make_float4(0.f, 0.f, 0.f, 0.f);

    int beg = offD[d], end = offD[d + 1];
    for (int i = beg; i < end; i++) {
        int2 p = pair[i];
        const float* eap = ea + (size_t)p.y * 5;
        float a0 = eap[0], a1 = eap[1], a2 = eap[2], a3 = eap[3], a4 = eap[4];
        float4 ev;
        ev.x = a0 * we0.x + a1 * we1.x + a2 * we2.x + a3 * we3.x + a4 * we4.x;
        ev.y = a0 * we0.y + a1 * we1.y + a2 * we2.y + a3 * we3.y + a4 * we4.y;
        ev.z = a0 * we0.z + a1 * we1.z + a2 * we2.z + a3 * we3.z + a4 * we4.z;
        ev.w = a0 * we0.w + a1 * we1.w + a2 * we2.w + a3 * we3.w + a4 * we4.w;
        const float4 kv = *(const float4*)&qkvs[(size_t)p.x * 512 + 128 + lane * 4];
        const float4 vv = *(const float4*)&qkvs[(size_t)p.x * 512 + 256 + lane * 4];
        float dot = qv.x * (kv.x + ev.x) + qv.y * (kv.y + ev.y) +
                    qv.z * (kv.z + ev.z) + qv.w * (kv.w + ev.w);
#pragma unroll
        for (int o = 16; o > 0; o >>= 1) dot += __shfl_xor_sync(0xffffffffu, dot, o);
        float lg = dot * 0.08838834764831845f;
        float mn = fmaxf(m, lg);
        float sc = __expf(m - mn);
        float pw = __expf(lg - mn);
        ssum = ssum * sc + pw;
        acc.x = acc.x * sc + pw * (vv.x + ev.x);
        acc.y = acc.y * sc + pw * (vv.y + ev.y);
        acc.z = acc.z * sc + pw * (vv.z + ev.z);
        acc.w = acc.w * sc + pw * (vv.w + ev.w);
        m = mn;
    }
    float inv = (ssum > 0.f) ? 1.f / ssum : 0.f;
    float4 skip = *(const float4*)&qkvs[(size_t)d * 512 + 384 + lane * 4];
    float4 o;
    o.x = fmaxf(acc.x * inv + skip.x, 0.f);
    o.y = fmaxf(acc.y * inv + skip.y, 0.f);
    o.z = fmaxf(acc.z * inv + skip.z, 0.f);
    o.w = fmaxf(acc.w * inv + skip.w, 0.f);
    *(float4*)&h[(size_t)d * Hh + lane * 4] = o;
}

// ---------------------------------------------------------------------------
// T1 = adj @ s1 via CSR gather — vectorized float4
// ---------------------------------------------------------------------------
__global__ void t1_gather_kernel(const int* __restrict__ offS, const int* __restrict__ dstsBySrc,
                                 const float* __restrict__ s1, float* __restrict__ T1) {
    int s = blockIdx.x * (blockDim.x >> 5) + (threadIdx.x >> 5);
    int lane = threadIdx.x & 31;
    if (s >= NT) return;
    float4 a0 = make_float4(0.f, 0.f, 0.f, 0.f);
    float4 a1 = make_float4(0.f, 0.f, 0.f, 0.f);
    int beg = offS[s], end = offS[s + 1];
    for (int i = beg; i < end; i++) {
        const float4* row = (const float4*)(s1 + (size_t)dstsBySrc[i] * K1);
        float4 r0 = row[lane], r1 = row[lane + 32];
        a0.x += r0.x; a0.y += r0.y; a0.z += r0.z; a0.w += r0.w;
        a1.x += r1.x; a1.y += r1.y; a1.z += r1.z; a1.w += r1.w;
    }
    float4* trow = (float4*)(T1 + (size_t)s * K1);
    trow[lane] = a0;
    trow[lane + 32] = a1;
}

// ---------------------------------------------------------------------------
// Per-graph tiled transpose
// ---------------------------------------------------------------------------
__global__ void transpose_pg_kernel(const float* __restrict__ in, float* __restrict__ outp,
                                    int R, int Cq) {
    __shared__ float tile[32][33];
    int b = blockIdx.z;
    int c0 = blockIdx.x * 32, r0 = blockIdx.y * 32;
    int tx = threadIdx.x, ty = threadIdx.y;
    const float* ip = in + (size_t)b * R * Cq;
    float* op = outp + (size_t)b * R * Cq;
#pragma unroll
    for (int i = 0; i < 32; i += 8)
        tile[ty + i][tx] = ip[(size_t)(r0 + ty + i) * Cq + c0 + tx];
    __syncthreads();
#pragma unroll
    for (int i = 0; i < 32; i += 8)
        op[(size_t)(c0 + ty + i) * R + r0 + tx] = tile[tx][ty + i];
}

// ---------------------------------------------------------------------------
// small FFMA GEMM for readout
// ---------------------------------------------------------------------------
template <int ACT>
__global__ void gemm64_kernel(const float* __restrict__ A, const float* __restrict__ Bm,
                              float* __restrict__ C, const float* __restrict__ bias,
                              int M, int N, int K, int lda, int ldb, int ldc) {
    constexpr int BM = 64, BN = 64, BK = 16;
    __shared__ float As[BK][BM + 1];
    __shared__ float Bs[BK][BN];
    int m0 = blockIdx.y * BM, n0 = blockIdx.x * BN;
    int t = threadIdx.x;
    int tx = t & 15, ty = t >> 4;
    float acc[4][4] = {};
    for (int k0 = 0; k0 < K; k0 += BK) {
        {
            int mm = t >> 2, kk = (t & 3) << 2;
            const float4 av = *(const float4*)&A[(size_t)(m0 + mm) * lda + k0 + kk];
            As[kk + 0][mm] = av.x; As[kk + 1][mm] = av.y;
            As[kk + 2][mm] = av.z; As[kk + 3][mm] = av.w;
        }
        {
            int kk = t >> 4, nn = (t & 15) << 2;
            *(float4*)&Bs[kk][nn] = *(const float4*)&Bm[(size_t)(k0 + kk) * ldb + n0 + nn];
        }
        __syncthreads();
#pragma unroll
        for (int kk = 0; kk < BK; kk++) {
            float a0 = As[kk][ty * 4 + 0], a1 = As[kk][ty * 4 + 1];
            float a2 = As[kk][ty * 4 + 2], a3 = As[kk][ty * 4 + 3];
            float4 b = *(const float4*)&Bs[kk][tx * 4];
            acc[0][0] += a0 * b.x; acc[0][1] += a0 * b.y; acc[0][2] += a0 * b.z; acc[0][3] += a0 * b.w;
            acc[1][0] += a1 * b.x; acc[1][1] += a1 * b.y; acc[1][2] += a1 * b.z; acc[1][3] += a1 * b.w;
            acc[2][0] += a2 * b.x; acc[2][1] += a2 * b.y; acc[2][2] += a2 * b.z; acc[2][3] += a2 * b.w;
            acc[3][0] += a3 * b.x; acc[3][1] += a3 * b.y; acc[3][2] += a3 * b.z; acc[3][3] += a3 * b.w;
        }
        __syncthreads();
    }
#pragma unroll
    for (int i = 0; i < 4; i++) {
        int m = m0 + ty * 4 + i;
        size_t off = (size_t)m * ldc + n0 + tx * 4;
        float4 r = make_float4(acc[i][0], acc[i][1], acc[i][2], acc[i][3]);
        if (bias) {
            int nb = n0 + tx * 4;
            r.x += bias[nb + 0]; r.y += bias[nb + 1];
            r.z += bias[nb + 2]; r.w += bias[nb + 3];
        }
        if (ACT == 1) {
            r.x = fmaxf(r.x, 0.f); r.y = fmaxf(r.y, 0.f);
            r.z = fmaxf(r.z, 0.f); r.w = fmaxf(r.w, 0.f);
        }
        *(float4*)&C[off] = r;
    }
}

// ---------------------------------------------------------------------------
// Softmax over rows
// ---------------------------------------------------------------------------
__global__ void softmax_rows_kernel(float* __restrict__ X, int rows, int cols) {
    int row = blockIdx.x * (blockDim.x >> 5) + (threadIdx.x >> 5);
    int lane = threadIdx.x & 31;
    if (row >= rows) return;
    float* p = X + (size_t)row * cols;
    float mx = -1e30f;
    for (int c = lane; c < cols; c += 32) mx = fmaxf(mx, p[c]);
#pragma unroll
    for (int o = 16; o > 0; o >>= 1) mx = fmaxf(mx, __shfl_xor_sync(0xffffffffu, mx, o));
    float sum = 0.f;
    for (int c = lane; c < cols; c += 32) {
        float v = __expf(p[c] - mx);
        p[c] = v;
        sum += v;
    }
#pragma unroll
    for (int o = 16; o > 0; o >>= 1) sum += __shfl_xor_sync(0xffffffffu, sum, o);
    float inv = 1.f / sum;
    for (int c = lane; c < cols; c += 32) p[c] *= inv;
}

// ---------------------------------------------------------------------------
// out_adj normalization
// ---------------------------------------------------------------------------
__global__ void adj_rowsum_kernel(float* __restrict__ A, float* __restrict__ d, int Kd) {
    int b = blockIdx.y, i = blockIdx.x, tid = threadIdx.x;
    float* row = A + ((size_t)b * Kd + i) * Kd;
    float v = row[tid];
    if (tid == i) { v = 0.f; row[tid] = 0.f; }
    __shared__ float sh[256];
    sh[tid] = v;
    __syncthreads();
    for (int s = Kd >> 1; s > 0; s >>= 1) {
        if (tid < s) sh[tid] += sh[tid + s];
        __syncthreads();
    }
    if (tid == 0) d[(size_t)b * Kd + i] = sqrtf(sh[0]) + 1e-15f;
}

__global__ void adj_divide_kernel(float* __restrict__ A, const float* __restrict__ d, int Kd,
                                  size_t total) {
    size_t i = (size_t)blockIdx.x * blockDim.x + threadIdx.x;
    if (i >= total) return;
    int j = (int)(i % Kd);
    size_t bi = i / Kd;
    int ii = (int)(bi % Kd);
    int b = (int)(bi / Kd);
    A[i] = A[i] / (d[(size_t)b * Kd + ii] * d[(size_t)b * Kd + j]);
}

// ---------------------------------------------------------------------------
// Readout
// ---------------------------------------------------------------------------
__global__ void mean_nodes_kernel(const float* __restrict__ xd, float* __restrict__ g) {
    int b = blockIdx.x, f = threadIdx.x;
    float s = 0.f;
    for (int n = 0; n < K2; n++) s += xd[((size_t)b * K2 + n) * Hh + f];
    g[(size_t)b * Hh + f] = s * (1.f / K2);
}

__global__ void readout_kernel(const float* __restrict__ g1, const float* __restrict__ Wro,
                               const float* __restrict__ bro, float* __restrict__ out) {
    int b = blockIdx.x, lane = threadIdx.x;
    float s = 0.f;
    for (int j = lane; j < Hh; j += 32) s += g1[(size_t)b * Hh + j] * Wro[j];
#pragma unroll
    for (int o = 16; o > 0; o >>= 1) s += __shfl_xor_sync(0xffffffffu, s, o);
    if (lane == 0) out[b] = 1.f / (1.f + expf(-(s + bro[0])));
}

// ---------------------------------------------------------------------------
// Host side
// ---------------------------------------------------------------------------
static void launch_gemm(int act, const float* A, const float* B, float* C,
                        const float* bias, const float* Cadd, int M, int N, int K, int lda,
                        int ldb, int ldc, long sA, long sB, long sC, int batch) {
    dim3 grid(N / 64, M / 128, batch), block(256);
    if (act == 1) {
        gemm_tc_kernel<1, false, false><<<grid, block>>>(A, B, nullptr, nullptr, C, bias, Cadd,
                                                         nullptr, nullptr,
                                                         M, N, K, lda, ldb, ldc, sA, sB, sC);
    } else {
        gemm_tc_kernel<0, false, false><<<grid, block>>>(A, B, nullptr, nullptr, C, bias, Cadd,
                                                         nullptr, nullptr,
                                                         M, N, K, lda, ldb, ldc, sA, sB, sC);
    }
}

static void launch_gemm_dual(int act, const float* A, const float* B, const float* A2,
                             const float* B2, float* C, const float* bias, int M, int N, int K,
                             int ld) {
    dim3 grid(N / 64, M / 128, 1), block(256);
    if (act == 1) {
        gemm_tc_kernel<1, true, false><<<grid, block>>>(A, B, A2, B2, C, bias, nullptr,
                                                        nullptr, nullptr,
                                                        M, N, K, ld, N, N, 0, 0, 0);
    } else {
        gemm_tc_kernel<0, true, false><<<grid, block>>>(A, B, A2, B2, C, bias, nullptr,
                                                        nullptr, nullptr,
                                                        M, N, K, ld, N, N, 0, 0, 0);
    }
}

extern "C" void kernel_launch(void* const* d_in, const int* in_sizes, int n_in,
                              void* d_out, int out_size) {
    const float* x      = (const float*)d_in[0];
    const int*   ei     = (const int*)d_in[1];
    const float* ea     = (const float*)d_in[2];
    const float* bng    = (const float*)d_in[4];
    const float* bnb    = (const float*)d_in[5];
    const float* Wq     = (const float*)d_in[6];
    const float* bq     = (const float*)d_in[7];
    const float* Wk     = (const float*)d_in[8];
    const float* bk     = (const float*)d_in[9];
    const float* Wv     = (const float*)d_in[10];
    const float* bv     = (const float*)d_in[11];
    const float* We     = (const float*)d_in[12];
    const float* Wskip  = (const float*)d_in[13];
    const float* bskip  = (const float*)d_in[14];
    const float* Wm1    = (const float*)d_in[15];
    const float* bm1    = (const float*)d_in[16];
    const float* W2rel  = (const float*)d_in[17];
    const float* b2rel  = (const float*)d_in[18];
    const float* W2root = (const float*)d_in[19];
    const float* Wm2    = (const float*)d_in[20];
    const float* bm2    = (const float*)d_in[21];
    const float* W3rel  = (const float*)d_in[22];
    const float* b3rel  = (const float*)d_in[23];
    const float* W3root = (const float*)d_in[24];
    const float* Wlin1  = (const float*)d_in[25];
    const float* blin1  = (const float*)d_in[26];
    const float* Wro    = (const float*)d_in[27];
    const float* bro    = (const float*)d_in[28];
    float* out = (float*)d_out;

    const int* src = ei;
    const int* dst = ei + Ee;

    float* gb = nullptr;
    cudaGetSymbolAddress((void**)&gb, GBUF);
    int* ib = (int*)(gb + O_INT);

    int*  cnt  = ib + I_CNT;
    int*  offS = ib + I_OFFS;
    int*  offD = ib + I_OFFD;
    int*  curS = ib + I_CURS;
    int*  curD = ib + I_CURD;
    int*  aux  = ib + I_AUX;
    int*  adjS = ib + I_ADJ;
    int2* pair = (int2*)(ib + I_PAIR);

    // launch 1: setup (wcat + zero cnt + zero bn sums)
    setup_kernel<<<(Cc * 512) / 256, 256>>>(Wq, Wk, Wv, Wskip, bq, bk, bv, bskip,
                                            gb + O_WCAT, gb + O_BCAT, cnt, gb + O_SUM);
    // launch 2-3: BatchNorm stats
    bn_reduce_kernel<<<256, Cc>>>(x, gb + O_SUM, gb + O_SSQ);
    bn_stats_kernel<<<1, Cc>>>(gb + O_SUM, gb + O_SSQ, bng, bnb);
    // launch 4: qkvs GEMM with fused BN prologue (PROFILED under -s 5 -c 1)
    {
        dim3 grid(512 / 64, NT / 128, 1), block(256);
        gemm_tc_kernel<0, false, true><<<grid, block>>>(
            x, gb + O_WCAT, nullptr, nullptr, gb + O_QKVS, gb + O_BCAT, nullptr,
            gb + O_SUM, gb + O_SSQ, NT, 512, Cc, Cc, 512, 512, 0, 0, 0);
    }

    // ---- CSR build ----
    csr_count_kernel<<<Ee / 256, 256>>>(src, dst, cnt);
    scan_chunk_kernel<<<256, 256>>>(cnt, ib + I_CURS, aux);
    scan_aux_kernel<<<1, 256>>>(aux);
    scan_final_kernel<<<256, 256>>>(ib + I_CURS, aux, offS, curS, offD, curD);
    csr_scatter_kernel<<<Ee / 256, 256>>>(src, dst, curS, curD, adjS, pair);

    // ---- fused attention ----
    attn_fused_kernel<<<NT / 8, 256>>>(offD, pair, ea, We, gb + O_QKVS, gb + O_HF);

    // ---- pool 1 ----
    launch_gemm(0, gb + O_HF, Wm1, gb + O_S1, bm1, nullptr,
                NT, K1, Hh, Hh, K1, K1, 0, 0, 0, 1);
    softmax_rows_kernel<<<NT / 8, 256>>>(gb + O_S1, NT, K1);

    {
        dim3 g(K1 / 32, Nn / 32, Bn), bdim(32, 8);
        transpose_pg_kernel<<<g, bdim>>>(gb + O_S1, gb + O_S1T, Nn, K1);
    }

    t1_gather_kernel<<<NT / 8, 256>>>(offS, adjS, gb + O_S1, gb + O_T1);

    launch_gemm(0, gb + O_S1T, gb + O_HF, gb + O_OX1, nullptr, nullptr,
                K1, Hh, Nn, Nn, Hh, Hh, (long)K1 * Nn, (long)Nn * Hh, (long)K1 * Hh, Bn);
    launch_gemm(0, gb + O_S1T, gb + O_T1, gb + O_OA1, nullptr, nullptr,
                K1, K1, Nn, Nn, K1, K1, (long)K1 * Nn, (long)Nn * K1, (long)K1 * K1, Bn);

    {
        dim3 g1(K1, Bn);
        adj_rowsum_kernel<<<g1, K1>>>(gb + O_OA1, gb + O_D1, K1);
        size_t tot = (size_t)Bn * K1 * K1;
        adj_divide_kernel<<<(int)((tot + 255) / 256), 256>>>(gb + O_OA1, gb + O_D1, K1, tot);
    }

    // ---- DenseGraphConv 2 ----
    launch_gemm(0, gb + O_OA1, gb + O_OX1, gb + O_AX1, nullptr, nullptr,
                K1, Hh, K1, K1, Hh, Hh, (long)K1 * K1, (long)K1 * Hh, (long)K1 * Hh, Bn);
    launch_gemm_dual(1, gb + O_AX1, W2rel, gb + O_OX1, W2root, gb + O_XD2, b2rel,
                     Bn * K1, Hh, Hh, Hh);

    // ---- pool 2 ----
    launch_gemm(0, gb + O_XD2, Wm2, gb + O_S2, bm2, nullptr,
                Bn * K1, K2, Hh, Hh, K2, K2, 0, 0, 0, 1);
    softmax_rows_kernel<<<(Bn * K1) / 8, 256>>>(gb + O_S2, Bn * K1, K2);

    {
        dim3 g(K2 / 32, K1 / 32, Bn), bdim(32, 8);
        transpose_pg_kernel<<<g, bdim>>>(gb + O_S2, gb + O_S2T, K1, K2);
    }

    launch_gemm(0, gb + O_S2T, gb + O_XD2, gb + O_OX2, nullptr, nullptr,
                K2, Hh, K1, K1, Hh, Hh, (long)K2 * K1, (long)K1 * Hh, (long)K2 * Hh, Bn);
    launch_gemm(0, gb + O_OA1, gb + O_S2, gb + O_T2, nullptr, nullptr,
                K1, K2, K1, K1, K2, K2, (long)K1 * K1, (long)K1 * K2, (long)K1 * K2, Bn);
    launch_gemm(0, gb + O_S2T, gb + O_T2, gb + O_OA2, nullptr, nullptr,
                K2, K2, K1, K1, K2, K2, (long)K2 * K1, (long)K1 * K2, (long)K2 * K2, Bn);

    {
        dim3 g2(K2, Bn);
        adj_rowsum_kernel<<<g2, K2>>>(gb + O_OA2, gb + O_D2, K2);
        size_t tot = (size_t)Bn * K2 * K2;
        adj_divide_kernel<<<(int)((tot + 255) / 256), 256>>>(gb + O_OA2, gb + O_D2, K2, tot);
    }

    // ---- DenseGraphConv 3 ----
    launch_gemm(0, gb + O_OA2, gb + O_OX2, gb + O_AX2, nullptr, nullptr,
                K2, Hh, K2, K2, Hh, Hh, (long)K2 * K2, (long)K2 * Hh, (long)K2 * Hh, Bn);
    launch_gemm_dual(0, gb + O_AX2, W3rel, gb + O_OX2, W3root, gb + O_XD3, b3rel,
                     Bn * K2, Hh, Hh, Hh);

    // ---- readout ----
    mean_nodes_kernel<<<Bn, Hh>>>(gb + O_XD3, gb + O_G);
    gemm64_kernel<1><<<dim3(2, 1), 256>>>(gb + O_G, Wlin1, gb + O_G1, blin1,
                                          Bn, Hh, Hh, Hh, Hh, Hh);
    readout_kernel<<<Bn, 32>>>(gb + O_G1, Wro, bro, out);
}